// round 1
// baseline (speedup 1.0000x reference)
#include <cuda_runtime.h>
#include <math.h>

#define H   1024
#define NH  16
#define HD  64
#define BSZ 2
#define SEQ 2048
#define MTOT (BSZ*SEQ)   // 4096 rows

// Scratch (allocation-free rule: __device__ globals)
__device__ float g_Q[MTOT * H];
__device__ float g_K[MTOT * H];
__device__ float g_V[MTOT * H];
__device__ float g_C[MTOT * H];

// ---------------------------------------------------------------------------
// SGEMM: C[M,N] = A[M,K] @ B[K,N] + bias[N]
// 128x128 tile, BK=8, 256 threads, 8x8 per-thread microtile.
// ---------------------------------------------------------------------------
__global__ __launch_bounds__(256) void sgemm_bias(
    const float* __restrict__ A, const float* __restrict__ Bm,
    const float* __restrict__ bias, float* __restrict__ C,
    int M, int N, int K)
{
    const int BM = 128, BN = 128, BK = 8;
    __shared__ float As[BK][BM];
    __shared__ float Bs[BK][BN];

    const int tid = threadIdx.x;
    const int bx = blockIdx.x;   // N tile
    const int by = blockIdx.y;   // M tile
    const int tx = tid & 15;
    const int ty = tid >> 4;

    float acc[8][8];
    #pragma unroll
    for (int i = 0; i < 8; i++)
        #pragma unroll
        for (int j = 0; j < 8; j++) acc[i][j] = 0.0f;

    const int a_row = tid >> 1;          // 0..127
    const int a_col = (tid & 1) * 4;     // 0 or 4
    const int b_row = tid >> 5;          // 0..7
    const int b_col = (tid & 31) * 4;    // 0..124

    const float* Ab = A + (size_t)(by * BM) * K;
    const float* Bb = Bm + bx * BN;

    for (int k0 = 0; k0 < K; k0 += BK) {
        float4 av = *(const float4*)&Ab[(size_t)a_row * K + k0 + a_col];
        As[a_col + 0][a_row] = av.x;
        As[a_col + 1][a_row] = av.y;
        As[a_col + 2][a_row] = av.z;
        As[a_col + 3][a_row] = av.w;
        *(float4*)&Bs[b_row][b_col] =
            *(const float4*)&Bb[(size_t)(k0 + b_row) * N + b_col];
        __syncthreads();

        #pragma unroll
        for (int k = 0; k < BK; k++) {
            float ar[8], br[8];
            *(float4*)(ar)     = *(const float4*)&As[k][ty * 8];
            *(float4*)(ar + 4) = *(const float4*)&As[k][ty * 8 + 4];
            *(float4*)(br)     = *(const float4*)&Bs[k][tx * 8];
            *(float4*)(br + 4) = *(const float4*)&Bs[k][tx * 8 + 4];
            #pragma unroll
            for (int i = 0; i < 8; i++)
                #pragma unroll
                for (int j = 0; j < 8; j++)
                    acc[i][j] = fmaf(ar[i], br[j], acc[i][j]);
        }
        __syncthreads();
    }

    const int cn = bx * BN + tx * 8;
    float bv[8];
    *(float4*)(bv)     = *(const float4*)&bias[cn];
    *(float4*)(bv + 4) = *(const float4*)&bias[cn + 4];
    #pragma unroll
    for (int i = 0; i < 8; i++) {
        int row = by * BM + ty * 8 + i;
        float4 o0 = { acc[i][0] + bv[0], acc[i][1] + bv[1],
                      acc[i][2] + bv[2], acc[i][3] + bv[3] };
        float4 o1 = { acc[i][4] + bv[4], acc[i][5] + bv[5],
                      acc[i][6] + bv[6], acc[i][7] + bv[7] };
        float4* dst = (float4*)&C[(size_t)row * N + cn];
        dst[0] = o0;
        dst[1] = o1;
    }
}

// ---------------------------------------------------------------------------
// Causal flash attention, fp32.
// grid: (SEQ/64, BSZ*NH), block 256.
// Per block: 64 q-rows of one head; stream KV tiles of 64 with online softmax.
// Thread grid 16x16; thread (tx,ty) owns score rows ty*4..+3, cols tx*4..+3.
// ---------------------------------------------------------------------------
__global__ __launch_bounds__(256) void attn_kernel(
    const float* __restrict__ Qg, const float* __restrict__ Kg,
    const float* __restrict__ Vg, float* __restrict__ Og)
{
    __shared__ float Qs[64 * 64];   // [i][d]
    __shared__ float Kt[64 * 64];   // [d][j]  (transposed)
    __shared__ float Vs[64 * 64];   // [j][d]
    __shared__ float Ps[64 * 64];   // [i][j]

    const int tid = threadIdx.x;
    const int tx  = tid & 15;
    const int ty  = tid >> 4;
    const int bh  = blockIdx.y;
    const int b   = bh / NH;
    const int h   = bh % NH;
    const int qb  = blockIdx.x;

    const size_t head_col = (size_t)h * HD;
    const float* Qbase = Qg + (size_t)b * SEQ * H + head_col;
    const float* Kbase = Kg + (size_t)b * SEQ * H + head_col;
    const float* Vbase = Vg + (size_t)b * SEQ * H + head_col;

    // Load Q tile (64x64): thread loads 4 float4s
    {
        const int r = tid >> 2;            // 0..63
        const int c0 = (tid & 3) * 16;     // 0,16,32,48
        #pragma unroll
        for (int it = 0; it < 4; it++) {
            int c = c0 + it * 4;
            *(float4*)&Qs[r * 64 + c] =
                *(const float4*)&Qbase[(size_t)(qb * 64 + r) * H + c];
        }
    }

    float m[4], l[4], acc[4][4];
    #pragma unroll
    for (int i = 0; i < 4; i++) {
        m[i] = -1e30f; l[i] = 0.0f;
        #pragma unroll
        for (int j = 0; j < 4; j++) acc[i][j] = 0.0f;
    }

    const float sc = 0.125f;  // 1/sqrt(64)
    const int nkb = qb + 1;   // causal: only tiles <= qb

    for (int kb = 0; kb < nkb; kb++) {
        __syncthreads();  // prior iter's Ps/Vs reads done before overwrite
        {
            const int r = tid >> 2;
            const int c0 = (tid & 3) * 16;
            #pragma unroll
            for (int it = 0; it < 4; it++) {
                int c = c0 + it * 4;
                float4 kv = *(const float4*)&Kbase[(size_t)(kb * 64 + r) * H + c];
                Kt[(c + 0) * 64 + r] = kv.x;
                Kt[(c + 1) * 64 + r] = kv.y;
                Kt[(c + 2) * 64 + r] = kv.z;
                Kt[(c + 3) * 64 + r] = kv.w;
                *(float4*)&Vs[r * 64 + c] =
                    *(const float4*)&Vbase[(size_t)(kb * 64 + r) * H + c];
            }
        }
        __syncthreads();

        // S tile = Q @ K^T (scaled)
        float s[4][4];
        #pragma unroll
        for (int i = 0; i < 4; i++)
            #pragma unroll
            for (int j = 0; j < 4; j++) s[i][j] = 0.0f;

        #pragma unroll 8
        for (int d = 0; d < 64; d++) {
            float qr[4], kr[4];
            #pragma unroll
            for (int i = 0; i < 4; i++) qr[i] = Qs[(ty * 4 + i) * 64 + d];
            *(float4*)kr = *(const float4*)&Kt[d * 64 + tx * 4];
            #pragma unroll
            for (int i = 0; i < 4; i++)
                #pragma unroll
                for (int j = 0; j < 4; j++)
                    s[i][j] = fmaf(qr[i], kr[j], s[i][j]);
        }

        // scale + causal mask (only diagonal tile needs masking)
        if (kb == qb) {
            #pragma unroll
            for (int i = 0; i < 4; i++)
                #pragma unroll
                for (int j = 0; j < 4; j++) {
                    int ig = ty * 4 + i, jg = tx * 4 + j;
                    s[i][j] = (jg > ig) ? -1e30f : s[i][j] * sc;
                }
        } else {
            #pragma unroll
            for (int i = 0; i < 4; i++)
                #pragma unroll
                for (int j = 0; j < 4; j++) s[i][j] *= sc;
        }

        // online softmax: row reductions across the 16 tx lanes
        float mn[4], rs[4], p[4][4];
        #pragma unroll
        for (int i = 0; i < 4; i++) {
            float tmax = s[i][0];
            #pragma unroll
            for (int j = 1; j < 4; j++) tmax = fmaxf(tmax, s[i][j]);
            #pragma unroll
            for (int off = 1; off < 16; off <<= 1)
                tmax = fmaxf(tmax, __shfl_xor_sync(0xffffffffu, tmax, off, 16));
            mn[i] = fmaxf(m[i], tmax);

            float rsum = 0.0f;
            #pragma unroll
            for (int j = 0; j < 4; j++) {
                p[i][j] = expf(s[i][j] - mn[i]);
                rsum += p[i][j];
            }
            #pragma unroll
            for (int off = 1; off < 16; off <<= 1)
                rsum += __shfl_xor_sync(0xffffffffu, rsum, off, 16);
            rs[i] = rsum;

            float scale = expf(m[i] - mn[i]);
            l[i] = l[i] * scale + rs[i];
            m[i] = mn[i];
            #pragma unroll
            for (int j = 0; j < 4; j++) acc[i][j] *= scale;
        }

        // stage P in smem for the PV product
        #pragma unroll
        for (int i = 0; i < 4; i++)
            #pragma unroll
            for (int j = 0; j < 4; j++)
                Ps[(ty * 4 + i) * 64 + tx * 4 + j] = p[i][j];
        __syncthreads();

        // acc += P @ V   (thread owns rows ty*4..+3, d-cols tx*4..+3)
        #pragma unroll 8
        for (int j = 0; j < 64; j++) {
            float pr[4], vr[4];
            #pragma unroll
            for (int i = 0; i < 4; i++) pr[i] = Ps[(ty * 4 + i) * 64 + j];
            *(float4*)vr = *(const float4*)&Vs[j * 64 + tx * 4];
            #pragma unroll
            for (int i = 0; i < 4; i++)
                #pragma unroll
                for (int jj = 0; jj < 4; jj++)
                    acc[i][jj] = fmaf(pr[i], vr[jj], acc[i][jj]);
        }
    }

    // epilogue: normalize and write ctx[b, s, h*HD + d]
    #pragma unroll
    for (int i = 0; i < 4; i++) {
        const float inv = 1.0f / l[i];
        const int row = qb * 64 + ty * 4 + i;
        float4 o = { acc[i][0] * inv, acc[i][1] * inv,
                     acc[i][2] * inv, acc[i][3] * inv };
        *(float4*)&Og[(size_t)b * SEQ * H + (size_t)row * H + head_col + tx * 4] = o;
    }
}

// ---------------------------------------------------------------------------
extern "C" void kernel_launch(void* const* d_in, const int* in_sizes, int n_in,
                              void* d_out, int out_size)
{
    const float* x  = (const float*)d_in[0];
    const float* Wq = (const float*)d_in[1];
    const float* bq = (const float*)d_in[2];
    const float* Wk = (const float*)d_in[3];
    const float* bk = (const float*)d_in[4];
    const float* Wv = (const float*)d_in[5];
    const float* bv = (const float*)d_in[6];
    const float* Wo = (const float*)d_in[7];
    const float* bo = (const float*)d_in[8];
    float* out = (float*)d_out;

    float *qbuf, *kbuf, *vbuf, *cbuf;
    cudaGetSymbolAddress((void**)&qbuf, g_Q);
    cudaGetSymbolAddress((void**)&kbuf, g_K);
    cudaGetSymbolAddress((void**)&vbuf, g_V);
    cudaGetSymbolAddress((void**)&cbuf, g_C);

    dim3 ggrid(H / 128, MTOT / 128);   // (8, 32)
    sgemm_bias<<<ggrid, 256>>>(x, Wq, bq, qbuf, MTOT, H, H);
    sgemm_bias<<<ggrid, 256>>>(x, Wk, bk, kbuf, MTOT, H, H);
    sgemm_bias<<<ggrid, 256>>>(x, Wv, bv, vbuf, MTOT, H, H);

    dim3 agrid(SEQ / 64, BSZ * NH);    // (32, 32)
    attn_kernel<<<agrid, 256>>>(qbuf, kbuf, vbuf, cbuf);

    sgemm_bias<<<ggrid, 256>>>(cbuf, Wo, bo, out, MTOT, H, H);
}

// round 3
// speedup vs baseline: 1.3348x; 1.3348x over previous
#include <cuda_runtime.h>
#include <cuda_bf16.h>
#include <math.h>
#include <stdint.h>

#define H   1024
#define NH  16
#define HD  64
#define BSZ 2
#define SEQ 2048
#define MTOT (BSZ*SEQ)   // 4096 rows

// ---------------------------------------------------------------------------
// Scratch (allocation-free rule: __device__ globals)
// ---------------------------------------------------------------------------
__device__ float g_Q[MTOT * H];
__device__ float g_K[MTOT * H];
__device__ float g_V[MTOT * H];
__device__ float g_C[MTOT * H];

__device__ __nv_bfloat16 g_xhi[MTOT * H];
__device__ __nv_bfloat16 g_xlo[MTOT * H];
__device__ __nv_bfloat16 g_chi[MTOT * H];
__device__ __nv_bfloat16 g_clo[MTOT * H];
__device__ __nv_bfloat16 g_WThi[4][H * H];   // W^T, bf16-hi, [N,K] K-major
__device__ __nv_bfloat16 g_WTlo[4][H * H];   // W^T, bf16-lo

// ---------------------------------------------------------------------------
// helpers
// ---------------------------------------------------------------------------
__device__ __forceinline__ uint32_t smem_u32(const void* p) {
    uint32_t a;
    asm("{ .reg .u64 t; cvta.to.shared.u64 t, %1; cvt.u32.u64 %0, t; }"
        : "=r"(a) : "l"(p));
    return a;
}

__device__ __forceinline__ void ldsm_x4(uint32_t* r, uint32_t addr) {
    asm volatile("ldmatrix.sync.aligned.m8n8.x4.shared.b16 {%0,%1,%2,%3}, [%4];"
                 : "=r"(r[0]), "=r"(r[1]), "=r"(r[2]), "=r"(r[3]) : "r"(addr));
}
__device__ __forceinline__ void ldsm_x2(uint32_t* r, uint32_t addr) {
    asm volatile("ldmatrix.sync.aligned.m8n8.x2.shared.b16 {%0,%1}, [%2];"
                 : "=r"(r[0]), "=r"(r[1]) : "r"(addr));
}
__device__ __forceinline__ void mma_bf16(float* c, const uint32_t* a,
                                         const uint32_t* b) {
    asm volatile(
        "mma.sync.aligned.m16n8k16.row.col.f32.bf16.bf16.f32 "
        "{%0,%1,%2,%3}, {%4,%5,%6,%7}, {%8,%9}, {%0,%1,%2,%3};"
        : "+f"(c[0]), "+f"(c[1]), "+f"(c[2]), "+f"(c[3])
        : "r"(a[0]), "r"(a[1]), "r"(a[2]), "r"(a[3]), "r"(b[0]), "r"(b[1]));
}

// ---------------------------------------------------------------------------
// Prep: fp32 -> bf16 hi/lo split
// ---------------------------------------------------------------------------
__global__ __launch_bounds__(256) void split_bf16(
    const float* __restrict__ src, __nv_bfloat16* __restrict__ hi,
    __nv_bfloat16* __restrict__ lo, int n)
{
    int i = blockIdx.x * 256 + threadIdx.x;
    if (i < n) {
        float v = src[i];
        __nv_bfloat16 h = __float2bfloat16(v);
        hi[i] = h;
        lo[i] = __float2bfloat16(v - __bfloat162float(h));
    }
}

// Prep: transpose W[K,N] -> W^T[N,K] with bf16 hi/lo split
__global__ __launch_bounds__(256) void transpose_split(
    const float* __restrict__ W, __nv_bfloat16* __restrict__ hi,
    __nv_bfloat16* __restrict__ lo)
{
    __shared__ float t[32][33];
    const int tx = threadIdx.x, ty = threadIdx.y;   // (32, 8)
    const int bx = blockIdx.x, by = blockIdx.y;
    #pragma unroll
    for (int i = 0; i < 4; i++)
        t[ty + 8 * i][tx] = W[(size_t)(by * 32 + ty + 8 * i) * H + bx * 32 + tx];
    __syncthreads();
    #pragma unroll
    for (int i = 0; i < 4; i++) {
        float v = t[tx][ty + 8 * i];                // = W[by*32+tx][bx*32+ty+8i]
        int n = bx * 32 + ty + 8 * i;
        int k = by * 32 + tx;
        __nv_bfloat16 h = __float2bfloat16(v);
        hi[(size_t)n * H + k] = h;
        lo[(size_t)n * H + k] = __float2bfloat16(v - __bfloat162float(h));
    }
}

// ---------------------------------------------------------------------------
// HMMA split-bf16 GEMM: C[M,1024] = A[M,1024] @ B + bias
// A as (Ahi, Alo) bf16 [M,K]; B as transposed (Bhi, Blo) bf16 [N,K] K-major.
// CTA: 128x128 tile, BK=32, 256 threads (8 warps, 2x4), warp tile 64x32.
// mma.m16n8k16 row.col; 3 split-products into one fp32 accumulator.
// Smem rows padded to 80B -> ldmatrix conflict-free. 40KB static smem.
// ---------------------------------------------------------------------------
#define ROWB 80                       // bytes per padded smem row (32 bf16 + pad)
#define TILEB (128 * ROWB)            // 10240 bytes per tile

__global__ __launch_bounds__(256) void gemm_hmma(
    const __nv_bfloat16* __restrict__ Ahi, const __nv_bfloat16* __restrict__ Alo,
    const __nv_bfloat16* __restrict__ Bhi, const __nv_bfloat16* __restrict__ Blo,
    const float* __restrict__ bias, float* __restrict__ C)
{
    __shared__ __align__(16) char smem[4 * TILEB];
    const uint32_t sb = smem_u32(smem);
    const uint32_t S_AHI = 0, S_ALO = TILEB, S_BHI = 2 * TILEB, S_BLO = 3 * TILEB;

    const int tid  = threadIdx.x;
    const int wid  = tid >> 5;
    const int lane = tid & 31;
    const int m0 = blockIdx.y * 128;
    const int n0 = blockIdx.x * 128;
    const int warp_m = wid >> 2;      // 0..1  -> m offset *64
    const int warp_n = wid & 3;       // 0..3  -> n offset *32

    float acc[4][4][4];
    #pragma unroll
    for (int i = 0; i < 4; i++)
        #pragma unroll
        for (int j = 0; j < 4; j++)
            #pragma unroll
            for (int r = 0; r < 4; r++) acc[i][j][r] = 0.0f;

    // per-thread ldmatrix source addresses (byte offsets within a tile)
    // A x4: 16 rows x 2 k-halves
    const uint32_t a_row = (lane & 7) + ((lane >> 3) & 1) * 8;   // + mf*16 + warp_m*64
    const uint32_t a_koff = (lane >> 4) * 16;                    // bytes (8 elems)
    // B x2: 8 rows x 2 k-halves (lanes 0-15 used)
    const uint32_t b_row = (lane & 7);                           // + nf*8 + warp_n*32
    const uint32_t b_koff = ((lane >> 3) & 1) * 16;              // bytes

    // global->smem: 512 uint4 per tile, 2 per thread
    const int g_row0 = tid >> 2;            // 0..63
    const int g_u4   = tid & 3;             // 0..3

    for (int kc = 0; kc < 32; kc++) {
        const int k0 = kc * 32;
        #pragma unroll
        for (int i = 0; i < 2; i++) {
            const int row = g_row0 + i * 64;
            const uint32_t so = (uint32_t)row * ROWB + g_u4 * 16;
            const size_t ga = (size_t)(m0 + row) * H + k0 + g_u4 * 8;
            const size_t gb = (size_t)(n0 + row) * H + k0 + g_u4 * 8;
            *(uint4*)(smem + S_AHI + so) = *(const uint4*)(Ahi + ga);
            *(uint4*)(smem + S_ALO + so) = *(const uint4*)(Alo + ga);
            *(uint4*)(smem + S_BHI + so) = *(const uint4*)(Bhi + gb);
            *(uint4*)(smem + S_BLO + so) = *(const uint4*)(Blo + gb);
        }
        __syncthreads();

        #pragma unroll
        for (int ks = 0; ks < 2; ks++) {
            const uint32_t kb = ks * 32;   // byte offset of 16-elem k-step

            // B fragments for all 4 n-frags, hi and lo
            uint32_t bh[4][2], bl[4][2];
            #pragma unroll
            for (int nf = 0; nf < 4; nf++) {
                const uint32_t boff =
                    (uint32_t)(warp_n * 32 + nf * 8 + b_row) * ROWB + kb + b_koff;
                ldsm_x2(bh[nf], sb + S_BHI + boff);
                ldsm_x2(bl[nf], sb + S_BLO + boff);
            }

            #pragma unroll
            for (int mf = 0; mf < 4; mf++) {
                const uint32_t aoff =
                    (uint32_t)(warp_m * 64 + mf * 16 + a_row) * ROWB + kb + a_koff;
                uint32_t ah[4], al[4];
                ldsm_x4(ah, sb + S_AHI + aoff);
                ldsm_x4(al, sb + S_ALO + aoff);
                #pragma unroll
                for (int nf = 0; nf < 4; nf++) {
                    mma_bf16(acc[mf][nf], ah, bh[nf]);
                    mma_bf16(acc[mf][nf], ah, bl[nf]);
                    mma_bf16(acc[mf][nf], al, bh[nf]);
                }
            }
        }
        __syncthreads();
    }

    // Epilogue: fragment layout -> global, with bias
    const int r_in = lane >> 2;          // 0..7
    const int c_in = (lane & 3) * 2;     // 0,2,4,6
    #pragma unroll
    for (int nf = 0; nf < 4; nf++) {
        const int col = n0 + warp_n * 32 + nf * 8 + c_in;
        const float2 bv = *(const float2*)(bias + col);
        #pragma unroll
        for (int mf = 0; mf < 4; mf++) {
            const int row = m0 + warp_m * 64 + mf * 16 + r_in;
            float2 o0 = { acc[mf][nf][0] + bv.x, acc[mf][nf][1] + bv.y };
            float2 o1 = { acc[mf][nf][2] + bv.x, acc[mf][nf][3] + bv.y };
            *(float2*)(C + (size_t)row * H + col) = o0;
            *(float2*)(C + (size_t)(row + 8) * H + col) = o1;
        }
    }
}

// ---------------------------------------------------------------------------
// Causal flash attention, fp32 (unchanged from R1).
// ---------------------------------------------------------------------------
__global__ __launch_bounds__(256) void attn_kernel(
    const float* __restrict__ Qg, const float* __restrict__ Kg,
    const float* __restrict__ Vg, float* __restrict__ Og)
{
    __shared__ float Qs[64 * 64];
    __shared__ float Kt[64 * 64];
    __shared__ float Vs[64 * 64];
    __shared__ float Ps[64 * 64];

    const int tid = threadIdx.x;
    const int tx  = tid & 15;
    const int ty  = tid >> 4;
    const int bh  = blockIdx.y;
    const int b   = bh / NH;
    const int h   = bh % NH;
    const int qb  = blockIdx.x;

    const size_t head_col = (size_t)h * HD;
    const float* Qbase = Qg + (size_t)b * SEQ * H + head_col;
    const float* Kbase = Kg + (size_t)b * SEQ * H + head_col;
    const float* Vbase = Vg + (size_t)b * SEQ * H + head_col;

    {
        const int r = tid >> 2;
        const int c0 = (tid & 3) * 16;
        #pragma unroll
        for (int it = 0; it < 4; it++) {
            int c = c0 + it * 4;
            *(float4*)&Qs[r * 64 + c] =
                *(const float4*)&Qbase[(size_t)(qb * 64 + r) * H + c];
        }
    }

    float m[4], l[4], acc[4][4];
    #pragma unroll
    for (int i = 0; i < 4; i++) {
        m[i] = -1e30f; l[i] = 0.0f;
        #pragma unroll
        for (int j = 0; j < 4; j++) acc[i][j] = 0.0f;
    }

    const float sc = 0.125f;
    const int nkb = qb + 1;

    for (int kb = 0; kb < nkb; kb++) {
        __syncthreads();
        {
            const int r = tid >> 2;
            const int c0 = (tid & 3) * 16;
            #pragma unroll
            for (int it = 0; it < 4; it++) {
                int c = c0 + it * 4;
                float4 kv = *(const float4*)&Kbase[(size_t)(kb * 64 + r) * H + c];
                Kt[(c + 0) * 64 + r] = kv.x;
                Kt[(c + 1) * 64 + r] = kv.y;
                Kt[(c + 2) * 64 + r] = kv.z;
                Kt[(c + 3) * 64 + r] = kv.w;
                *(float4*)&Vs[r * 64 + c] =
                    *(const float4*)&Vbase[(size_t)(kb * 64 + r) * H + c];
            }
        }
        __syncthreads();

        float s[4][4];
        #pragma unroll
        for (int i = 0; i < 4; i++)
            #pragma unroll
            for (int j = 0; j < 4; j++) s[i][j] = 0.0f;

        #pragma unroll 8
        for (int d = 0; d < 64; d++) {
            float qr[4], kr[4];
            #pragma unroll
            for (int i = 0; i < 4; i++) qr[i] = Qs[(ty * 4 + i) * 64 + d];
            *(float4*)kr = *(const float4*)&Kt[d * 64 + tx * 4];
            #pragma unroll
            for (int i = 0; i < 4; i++)
                #pragma unroll
                for (int j = 0; j < 4; j++)
                    s[i][j] = fmaf(qr[i], kr[j], s[i][j]);
        }

        if (kb == qb) {
            #pragma unroll
            for (int i = 0; i < 4; i++)
                #pragma unroll
                for (int j = 0; j < 4; j++) {
                    int ig = ty * 4 + i, jg = tx * 4 + j;
                    s[i][j] = (jg > ig) ? -1e30f : s[i][j] * sc;
                }
        } else {
            #pragma unroll
            for (int i = 0; i < 4; i++)
                #pragma unroll
                for (int j = 0; j < 4; j++) s[i][j] *= sc;
        }

        float mn[4], rs[4], p[4][4];
        #pragma unroll
        for (int i = 0; i < 4; i++) {
            float tmax = s[i][0];
            #pragma unroll
            for (int j = 1; j < 4; j++) tmax = fmaxf(tmax, s[i][j]);
            #pragma unroll
            for (int off = 1; off < 16; off <<= 1)
                tmax = fmaxf(tmax, __shfl_xor_sync(0xffffffffu, tmax, off, 16));
            mn[i] = fmaxf(m[i], tmax);

            float rsum = 0.0f;
            #pragma unroll
            for (int j = 0; j < 4; j++) {
                p[i][j] = expf(s[i][j] - mn[i]);
                rsum += p[i][j];
            }
            #pragma unroll
            for (int off = 1; off < 16; off <<= 1)
                rsum += __shfl_xor_sync(0xffffffffu, rsum, off, 16);
            rs[i] = rsum;

            float scale = expf(m[i] - mn[i]);
            l[i] = l[i] * scale + rs[i];
            m[i] = mn[i];
            #pragma unroll
            for (int j = 0; j < 4; j++) acc[i][j] *= scale;
        }

        #pragma unroll
        for (int i = 0; i < 4; i++)
            #pragma unroll
            for (int j = 0; j < 4; j++)
                Ps[(ty * 4 + i) * 64 + tx * 4 + j] = p[i][j];
        __syncthreads();

        #pragma unroll 8
        for (int j = 0; j < 64; j++) {
            float pr[4], vr[4];
            #pragma unroll
            for (int i = 0; i < 4; i++) pr[i] = Ps[(ty * 4 + i) * 64 + j];
            *(float4*)vr = *(const float4*)&Vs[j * 64 + tx * 4];
            #pragma unroll
            for (int i = 0; i < 4; i++)
                #pragma unroll
                for (int jj = 0; jj < 4; jj++)
                    acc[i][jj] = fmaf(pr[i], vr[jj], acc[i][jj]);
        }
    }

    #pragma unroll
    for (int i = 0; i < 4; i++) {
        const float inv = 1.0f / l[i];
        const int row = qb * 64 + ty * 4 + i;
        float4 o = { acc[i][0] * inv, acc[i][1] * inv,
                     acc[i][2] * inv, acc[i][3] * inv };
        *(float4*)&Og[(size_t)b * SEQ * H + (size_t)row * H + head_col + tx * 4] = o;
    }
}

// ---------------------------------------------------------------------------
extern "C" void kernel_launch(void* const* d_in, const int* in_sizes, int n_in,
                              void* d_out, int out_size)
{
    const float* x  = (const float*)d_in[0];
    const float* Wq = (const float*)d_in[1];
    const float* bq = (const float*)d_in[2];
    const float* Wk = (const float*)d_in[3];
    const float* bk = (const float*)d_in[4];
    const float* Wv = (const float*)d_in[5];
    const float* bv = (const float*)d_in[6];
    const float* Wo = (const float*)d_in[7];
    const float* bo = (const float*)d_in[8];
    float* out = (float*)d_out;

    float *qbuf, *kbuf, *vbuf, *cbuf;
    cudaGetSymbolAddress((void**)&qbuf, g_Q);
    cudaGetSymbolAddress((void**)&kbuf, g_K);
    cudaGetSymbolAddress((void**)&vbuf, g_V);
    cudaGetSymbolAddress((void**)&cbuf, g_C);
    __nv_bfloat16 *xhi, *xlo, *chi, *clo, *wthi, *wtlo;
    cudaGetSymbolAddress((void**)&xhi, g_xhi);
    cudaGetSymbolAddress((void**)&xlo, g_xlo);
    cudaGetSymbolAddress((void**)&chi, g_chi);
    cudaGetSymbolAddress((void**)&clo, g_clo);
    cudaGetSymbolAddress((void**)&wthi, g_WThi);
    cudaGetSymbolAddress((void**)&wtlo, g_WTlo);

    const int nelem = MTOT * H;

    // Prep: split activations, transpose+split weights
    split_bf16<<<(nelem + 255) / 256, 256>>>(x, xhi, xlo, nelem);
    dim3 tgrid(H / 32, H / 32), tblk(32, 8);
    transpose_split<<<tgrid, tblk>>>(Wq, wthi + 0 * (size_t)H * H, wtlo + 0 * (size_t)H * H);
    transpose_split<<<tgrid, tblk>>>(Wk, wthi + 1 * (size_t)H * H, wtlo + 1 * (size_t)H * H);
    transpose_split<<<tgrid, tblk>>>(Wv, wthi + 2 * (size_t)H * H, wtlo + 2 * (size_t)H * H);
    transpose_split<<<tgrid, tblk>>>(Wo, wthi + 3 * (size_t)H * H, wtlo + 3 * (size_t)H * H);

    // Q/K/V projections on HMMA tensor cores
    dim3 ggrid(H / 128, MTOT / 128);   // (8, 32)
    gemm_hmma<<<ggrid, 256>>>(xhi, xlo,
        wthi + 0 * (size_t)H * H, wtlo + 0 * (size_t)H * H, bq, qbuf);
    gemm_hmma<<<ggrid, 256>>>(xhi, xlo,
        wthi + 1 * (size_t)H * H, wtlo + 1 * (size_t)H * H, bk, kbuf);
    gemm_hmma<<<ggrid, 256>>>(xhi, xlo,
        wthi + 2 * (size_t)H * H, wtlo + 2 * (size_t)H * H, bv, vbuf);

    // Attention (fp32)
    dim3 agrid(SEQ / 64, BSZ * NH);
    attn_kernel<<<agrid, 256>>>(qbuf, kbuf, vbuf, cbuf);

    // Output projection
    split_bf16<<<(nelem + 255) / 256, 256>>>(cbuf, chi, clo, nelem);
    gemm_hmma<<<ggrid, 256>>>(chi, clo,
        wthi + 3 * (size_t)H * H, wtlo + 3 * (size_t)H * H, bo, out);
}

// round 4
// speedup vs baseline: 2.2779x; 1.7066x over previous
#include <cuda_runtime.h>
#include <cuda_bf16.h>
#include <math.h>
#include <stdint.h>

#define H   1024
#define NH  16
#define HD  64
#define BSZ 2
#define SEQ 2048
#define MTOT (BSZ*SEQ)   // 4096 rows

// 0.125 (1/sqrt(HD)) * log2(e): folded into Q projection
#define QSCALE 0.18033688011112042f

// ---------------------------------------------------------------------------
// Scratch (allocation-free rule: __device__ globals)
// ---------------------------------------------------------------------------
__device__ __nv_bfloat16 g_Qhi[MTOT * H];
__device__ __nv_bfloat16 g_Qlo[MTOT * H];
__device__ __nv_bfloat16 g_Khi[MTOT * H];
__device__ __nv_bfloat16 g_Klo[MTOT * H];
__device__ __nv_bfloat16 g_Vhi[MTOT * H];
__device__ __nv_bfloat16 g_Vlo[MTOT * H];
__device__ __nv_bfloat16 g_chi[MTOT * H];
__device__ __nv_bfloat16 g_clo[MTOT * H];
__device__ __nv_bfloat16 g_xhi[MTOT * H];
__device__ __nv_bfloat16 g_xlo[MTOT * H];
__device__ __nv_bfloat16 g_WThi[4][H * H];   // W^T, bf16-hi, [N,K] K-major
__device__ __nv_bfloat16 g_WTlo[4][H * H];   // W^T, bf16-lo

// ---------------------------------------------------------------------------
// helpers
// ---------------------------------------------------------------------------
__device__ __forceinline__ uint32_t smem_u32(const void* p) {
    uint32_t a;
    asm("{ .reg .u64 t; cvta.to.shared.u64 t, %1; cvt.u32.u64 %0, t; }"
        : "=r"(a) : "l"(p));
    return a;
}
__device__ __forceinline__ void ldsm_x4(uint32_t* r, uint32_t addr) {
    asm volatile("ldmatrix.sync.aligned.m8n8.x4.shared.b16 {%0,%1,%2,%3}, [%4];"
                 : "=r"(r[0]), "=r"(r[1]), "=r"(r[2]), "=r"(r[3]) : "r"(addr));
}
__device__ __forceinline__ void ldsm_x2(uint32_t* r, uint32_t addr) {
    asm volatile("ldmatrix.sync.aligned.m8n8.x2.shared.b16 {%0,%1}, [%2];"
                 : "=r"(r[0]), "=r"(r[1]) : "r"(addr));
}
__device__ __forceinline__ void ldsm_x2t(uint32_t* r, uint32_t addr) {
    asm volatile("ldmatrix.sync.aligned.m8n8.x2.trans.shared.b16 {%0,%1}, [%2];"
                 : "=r"(r[0]), "=r"(r[1]) : "r"(addr));
}
__device__ __forceinline__ void mma_bf16(float* c, const uint32_t* a,
                                         const uint32_t* b) {
    asm volatile(
        "mma.sync.aligned.m16n8k16.row.col.f32.bf16.bf16.f32 "
        "{%0,%1,%2,%3}, {%4,%5,%6,%7}, {%8,%9}, {%0,%1,%2,%3};"
        : "+f"(c[0]), "+f"(c[1]), "+f"(c[2]), "+f"(c[3])
        : "r"(a[0]), "r"(a[1]), "r"(a[2]), "r"(a[3]), "r"(b[0]), "r"(b[1]));
}
__device__ __forceinline__ float exp2a(float x) {
    float y;
    asm("ex2.approx.f32 %0, %1;" : "=f"(y) : "f"(x));
    return y;
}
// pack two floats -> bf16x2 (hi) and residual bf16x2 (lo)
__device__ __forceinline__ void split2(float a, float b, uint32_t& hi, uint32_t& lo) {
    __nv_bfloat162 h = __floats2bfloat162_rn(a, b);
    float ra = a - __bfloat162float(h.x);
    float rb = b - __bfloat162float(h.y);
    __nv_bfloat162 l = __floats2bfloat162_rn(ra, rb);
    hi = *(uint32_t*)&h;
    lo = *(uint32_t*)&l;
}

// ---------------------------------------------------------------------------
// Prep
// ---------------------------------------------------------------------------
__global__ __launch_bounds__(256) void split_bf16(
    const float* __restrict__ src, __nv_bfloat16* __restrict__ hi,
    __nv_bfloat16* __restrict__ lo, int n)
{
    int i = blockIdx.x * 256 + threadIdx.x;
    if (i < n) {
        float v = src[i];
        __nv_bfloat16 h = __float2bfloat16(v);
        hi[i] = h;
        lo[i] = __float2bfloat16(v - __bfloat162float(h));
    }
}

__global__ __launch_bounds__(256) void transpose_split(
    const float* __restrict__ W, __nv_bfloat16* __restrict__ hi,
    __nv_bfloat16* __restrict__ lo)
{
    __shared__ float t[32][33];
    const int tx = threadIdx.x, ty = threadIdx.y;   // (32, 8)
    const int bx = blockIdx.x, by = blockIdx.y;
    #pragma unroll
    for (int i = 0; i < 4; i++)
        t[ty + 8 * i][tx] = W[(size_t)(by * 32 + ty + 8 * i) * H + bx * 32 + tx];
    __syncthreads();
    #pragma unroll
    for (int i = 0; i < 4; i++) {
        float v = t[tx][ty + 8 * i];
        int n = bx * 32 + ty + 8 * i;
        int k = by * 32 + tx;
        __nv_bfloat16 h = __float2bfloat16(v);
        hi[(size_t)n * H + k] = h;
        lo[(size_t)n * H + k] = __float2bfloat16(v - __bfloat162float(h));
    }
}

// ---------------------------------------------------------------------------
// HMMA split-bf16 GEMM core. Two epilogues:
//   gemm_hmma_f32   : C = A@B + bias            (fp32 out)
//   gemm_hmma_split : (hi,lo) = split(scale*(A@B + bias))
// CTA 128x128, BK=32, 256 thr (8 warps 2x4), warp tile 64x32.
// ---------------------------------------------------------------------------
#define ROWB 80
#define TILEB (128 * ROWB)

template <bool SPLIT>
__device__ __forceinline__ void gemm_body(
    const __nv_bfloat16* __restrict__ Ahi, const __nv_bfloat16* __restrict__ Alo,
    const __nv_bfloat16* __restrict__ Bhi, const __nv_bfloat16* __restrict__ Blo,
    const float* __restrict__ bias, float scale,
    float* __restrict__ Cf, __nv_bfloat16* __restrict__ Chi,
    __nv_bfloat16* __restrict__ Clo)
{
    __shared__ __align__(16) char smem[4 * TILEB];
    const uint32_t sb = smem_u32(smem);
    const uint32_t S_AHI = 0, S_ALO = TILEB, S_BHI = 2 * TILEB, S_BLO = 3 * TILEB;

    const int tid  = threadIdx.x;
    const int wid  = tid >> 5;
    const int lane = tid & 31;
    const int m0 = blockIdx.y * 128;
    const int n0 = blockIdx.x * 128;
    const int warp_m = wid >> 2;
    const int warp_n = wid & 3;

    float acc[4][4][4];
    #pragma unroll
    for (int i = 0; i < 4; i++)
        #pragma unroll
        for (int j = 0; j < 4; j++)
            #pragma unroll
            for (int r = 0; r < 4; r++) acc[i][j][r] = 0.0f;

    const uint32_t a_row = (lane & 15);
    const uint32_t a_koff = (lane >> 4) * 16;
    const uint32_t b_row = (lane & 7);
    const uint32_t b_koff = ((lane >> 3) & 1) * 16;

    const int g_row0 = tid >> 2;
    const int g_u4   = tid & 3;

    for (int kc = 0; kc < 32; kc++) {
        const int k0 = kc * 32;
        #pragma unroll
        for (int i = 0; i < 2; i++) {
            const int row = g_row0 + i * 64;
            const uint32_t so = (uint32_t)row * ROWB + g_u4 * 16;
            const size_t ga = (size_t)(m0 + row) * H + k0 + g_u4 * 8;
            const size_t gb = (size_t)(n0 + row) * H + k0 + g_u4 * 8;
            *(uint4*)(smem + S_AHI + so) = *(const uint4*)(Ahi + ga);
            *(uint4*)(smem + S_ALO + so) = *(const uint4*)(Alo + ga);
            *(uint4*)(smem + S_BHI + so) = *(const uint4*)(Bhi + gb);
            *(uint4*)(smem + S_BLO + so) = *(const uint4*)(Blo + gb);
        }
        __syncthreads();

        #pragma unroll
        for (int ks = 0; ks < 2; ks++) {
            const uint32_t kb = ks * 32;
            uint32_t bh[4][2], bl[4][2];
            #pragma unroll
            for (int nf = 0; nf < 4; nf++) {
                const uint32_t boff =
                    (uint32_t)(warp_n * 32 + nf * 8 + b_row) * ROWB + kb + b_koff;
                ldsm_x2(bh[nf], sb + S_BHI + boff);
                ldsm_x2(bl[nf], sb + S_BLO + boff);
            }
            #pragma unroll
            for (int mf = 0; mf < 4; mf++) {
                const uint32_t aoff =
                    (uint32_t)(warp_m * 64 + mf * 16 + a_row) * ROWB + kb + a_koff;
                uint32_t ah[4], al[4];
                ldsm_x4(ah, sb + S_AHI + aoff);
                ldsm_x4(al, sb + S_ALO + aoff);
                #pragma unroll
                for (int nf = 0; nf < 4; nf++) {
                    mma_bf16(acc[mf][nf], ah, bh[nf]);
                    mma_bf16(acc[mf][nf], ah, bl[nf]);
                    mma_bf16(acc[mf][nf], al, bh[nf]);
                }
            }
        }
        __syncthreads();
    }

    const int r_in = lane >> 2;
    const int c_in = (lane & 3) * 2;
    #pragma unroll
    for (int nf = 0; nf < 4; nf++) {
        const int col = n0 + warp_n * 32 + nf * 8 + c_in;
        const float2 bv = *(const float2*)(bias + col);
        #pragma unroll
        for (int mf = 0; mf < 4; mf++) {
            const int row = m0 + warp_m * 64 + mf * 16 + r_in;
            float v00 = (acc[mf][nf][0] + bv.x) * scale;
            float v01 = (acc[mf][nf][1] + bv.y) * scale;
            float v10 = (acc[mf][nf][2] + bv.x) * scale;
            float v11 = (acc[mf][nf][3] + bv.y) * scale;
            if (SPLIT) {
                uint32_t h0, l0, h1, l1;
                split2(v00, v01, h0, l0);
                split2(v10, v11, h1, l1);
                *(uint32_t*)(Chi + (size_t)row * H + col) = h0;
                *(uint32_t*)(Clo + (size_t)row * H + col) = l0;
                *(uint32_t*)(Chi + (size_t)(row + 8) * H + col) = h1;
                *(uint32_t*)(Clo + (size_t)(row + 8) * H + col) = l1;
            } else {
                float2 o0 = { v00, v01 };
                float2 o1 = { v10, v11 };
                *(float2*)(Cf + (size_t)row * H + col) = o0;
                *(float2*)(Cf + (size_t)(row + 8) * H + col) = o1;
            }
        }
    }
}

__global__ __launch_bounds__(256) void gemm_hmma_f32(
    const __nv_bfloat16* __restrict__ Ahi, const __nv_bfloat16* __restrict__ Alo,
    const __nv_bfloat16* __restrict__ Bhi, const __nv_bfloat16* __restrict__ Blo,
    const float* __restrict__ bias, float* __restrict__ C)
{
    gemm_body<false>(Ahi, Alo, Bhi, Blo, bias, 1.0f, C, nullptr, nullptr);
}

__global__ __launch_bounds__(256) void gemm_hmma_split(
    const __nv_bfloat16* __restrict__ Ahi, const __nv_bfloat16* __restrict__ Alo,
    const __nv_bfloat16* __restrict__ Bhi, const __nv_bfloat16* __restrict__ Blo,
    const float* __restrict__ bias, float scale,
    __nv_bfloat16* __restrict__ Chi, __nv_bfloat16* __restrict__ Clo)
{
    gemm_body<true>(Ahi, Alo, Bhi, Blo, bias, scale, nullptr, Chi, Clo);
}

// ---------------------------------------------------------------------------
// HMMA flash attention (split bf16, fp32 softmax in log2 domain).
// grid (SEQ/64, BSZ*NH), 128 threads (4 warps). Warp w owns q rows w*16..+15.
// KV tiles of 32. Q pre-scaled by 0.125*log2e in projection.
// ---------------------------------------------------------------------------
#define AROW 144                       // 64 bf16 row + 16B pad
#define QTILE (64 * AROW)              // 9216
#define KVTILE (32 * AROW)             // 4608

__global__ __launch_bounds__(128) void attn_hmma(
    const __nv_bfloat16* __restrict__ Qhi, const __nv_bfloat16* __restrict__ Qlo,
    const __nv_bfloat16* __restrict__ Khi, const __nv_bfloat16* __restrict__ Klo,
    const __nv_bfloat16* __restrict__ Vhi, const __nv_bfloat16* __restrict__ Vlo,
    __nv_bfloat16* __restrict__ Chi, __nv_bfloat16* __restrict__ Clo)
{
    __shared__ __align__(16) char smem[2 * QTILE + 4 * KVTILE];   // 36864 B
    const uint32_t sb = smem_u32(smem);
    const uint32_t S_QH = 0, S_QL = QTILE;
    const uint32_t S_KH = 2 * QTILE, S_KL = S_KH + KVTILE;
    const uint32_t S_VH = S_KL + KVTILE, S_VL = S_VH + KVTILE;

    const int tid  = threadIdx.x;
    const int warp = tid >> 5;
    const int lane = tid & 31;
    const int qb = blockIdx.x;
    const int b  = blockIdx.y / NH;
    const int h  = blockIdx.y % NH;
    const size_t hcol = (size_t)h * HD;
    const size_t rbase = (size_t)b * SEQ;

    // Load Q tile (64 x 64 bf16, hi+lo)
    #pragma unroll
    for (int t = 0; t < 4; t++) {
        const int idx = tid + t * 128;          // 0..511
        const int r = idx >> 3, c = idx & 7;
        const uint32_t so = (uint32_t)r * AROW + c * 16;
        const size_t g = (rbase + qb * 64 + r) * H + hcol + c * 8;
        *(uint4*)(smem + S_QH + so) = *(const uint4*)(Qhi + g);
        *(uint4*)(smem + S_QL + so) = *(const uint4*)(Qlo + g);
    }

    float O[8][4];
    #pragma unroll
    for (int d = 0; d < 8; d++)
        #pragma unroll
        for (int r = 0; r < 4; r++) O[d][r] = 0.0f;
    float m0 = -1e30f, m1 = -1e30f, l0 = 0.0f, l1 = 0.0f;

    const uint32_t a_base = S_QH + (uint32_t)(warp * 16 + (lane & 15)) * AROW
                          + (lane >> 4) * 16;
    const uint32_t al_base = a_base + (S_QL - S_QH);
    const uint32_t b_rowoff = (uint32_t)(lane & 7) * AROW + ((lane >> 3) & 1) * 16;
    const uint32_t v_laneoff = (uint32_t)(lane & 15) * AROW;

    const int r_in = lane >> 2;                 // fragment rows r_in, r_in+8
    const int c_in = (lane & 3) * 2;

    const int nkb = 2 * qb + 2;
    for (int kb = 0; kb < nkb; kb++) {
        if (kb > 0) __syncthreads();
        // load K/V tiles (32 x 64 bf16, hi+lo each)
        #pragma unroll
        for (int t = 0; t < 2; t++) {
            const int idx = tid + t * 128;      // 0..255
            const int r = idx >> 3, c = idx & 7;
            const uint32_t so = (uint32_t)r * AROW + c * 16;
            const size_t g = (rbase + kb * 32 + r) * H + hcol + c * 8;
            *(uint4*)(smem + S_KH + so) = *(const uint4*)(Khi + g);
            *(uint4*)(smem + S_KL + so) = *(const uint4*)(Klo + g);
            *(uint4*)(smem + S_VH + so) = *(const uint4*)(Vhi + g);
            *(uint4*)(smem + S_VL + so) = *(const uint4*)(Vlo + g);
        }
        __syncthreads();

        // S = Q K^T (log2-domain scaled already)
        float s[4][4];
        #pragma unroll
        for (int nf = 0; nf < 4; nf++)
            #pragma unroll
            for (int r = 0; r < 4; r++) s[nf][r] = 0.0f;

        #pragma unroll
        for (int ks = 0; ks < 4; ks++) {
            uint32_t ah[4], al[4];
            ldsm_x4(ah, sb + a_base + ks * 32);
            ldsm_x4(al, sb + al_base + ks * 32);
            #pragma unroll
            for (int nf = 0; nf < 4; nf++) {
                uint32_t bh[2], bl[2];
                const uint32_t bo = (uint32_t)(nf * 8) * AROW + b_rowoff + ks * 32;
                ldsm_x2(bh, sb + S_KH + bo);
                ldsm_x2(bl, sb + S_KL + bo);
                mma_bf16(s[nf], ah, bh);
                mma_bf16(s[nf], ah, bl);
                mma_bf16(s[nf], al, bh);
            }
        }

        // causal mask (only tiles touching the diagonal)
        if (kb >= 2 * qb) {
            const int row0 = qb * 64 + warp * 16 + r_in;
            const int row1 = row0 + 8;
            #pragma unroll
            for (int nf = 0; nf < 4; nf++) {
                const int cg = kb * 32 + nf * 8 + c_in;
                if (cg > row0)     s[nf][0] = -1e30f;
                if (cg + 1 > row0) s[nf][1] = -1e30f;
                if (cg > row1)     s[nf][2] = -1e30f;
                if (cg + 1 > row1) s[nf][3] = -1e30f;
            }
        }

        // online softmax
        float rmax0 = -1e30f, rmax1 = -1e30f;
        #pragma unroll
        for (int nf = 0; nf < 4; nf++) {
            rmax0 = fmaxf(rmax0, fmaxf(s[nf][0], s[nf][1]));
            rmax1 = fmaxf(rmax1, fmaxf(s[nf][2], s[nf][3]));
        }
        rmax0 = fmaxf(rmax0, __shfl_xor_sync(0xffffffffu, rmax0, 1));
        rmax0 = fmaxf(rmax0, __shfl_xor_sync(0xffffffffu, rmax0, 2));
        rmax1 = fmaxf(rmax1, __shfl_xor_sync(0xffffffffu, rmax1, 1));
        rmax1 = fmaxf(rmax1, __shfl_xor_sync(0xffffffffu, rmax1, 2));
        const float mn0 = fmaxf(m0, rmax0);
        const float mn1 = fmaxf(m1, rmax1);
        const float sc0 = exp2a(m0 - mn0);
        const float sc1 = exp2a(m1 - mn1);

        float rs0 = 0.0f, rs1 = 0.0f;
        uint32_t phi01[4], phi23[4], plo01[4], plo23[4];
        #pragma unroll
        for (int nf = 0; nf < 4; nf++) {
            float p00 = exp2a(s[nf][0] - mn0);
            float p01 = exp2a(s[nf][1] - mn0);
            float p10 = exp2a(s[nf][2] - mn1);
            float p11 = exp2a(s[nf][3] - mn1);
            rs0 += p00 + p01;
            rs1 += p10 + p11;
            split2(p00, p01, phi01[nf], plo01[nf]);
            split2(p10, p11, phi23[nf], plo23[nf]);
        }
        rs0 += __shfl_xor_sync(0xffffffffu, rs0, 1);
        rs0 += __shfl_xor_sync(0xffffffffu, rs0, 2);
        rs1 += __shfl_xor_sync(0xffffffffu, rs1, 1);
        rs1 += __shfl_xor_sync(0xffffffffu, rs1, 2);
        l0 = l0 * sc0 + rs0;
        l1 = l1 * sc1 + rs1;
        m0 = mn0; m1 = mn1;
        #pragma unroll
        for (int d = 0; d < 8; d++) {
            O[d][0] *= sc0; O[d][1] *= sc0;
            O[d][2] *= sc1; O[d][3] *= sc1;
        }

        // O += P V  (P A-frags from registers; V via ldmatrix.trans)
        #pragma unroll
        for (int ksj = 0; ksj < 2; ksj++) {
            const uint32_t ph[4] = { phi01[2*ksj], phi23[2*ksj],
                                     phi01[2*ksj+1], phi23[2*ksj+1] };
            const uint32_t pl[4] = { plo01[2*ksj], plo23[2*ksj],
                                     plo01[2*ksj+1], plo23[2*ksj+1] };
            const uint32_t vbase = (uint32_t)(ksj * 16) * AROW + v_laneoff;
            #pragma unroll
            for (int df = 0; df < 8; df++) {
                uint32_t vh[2], vl[2];
                ldsm_x2t(vh, sb + S_VH + vbase + df * 16);
                ldsm_x2t(vl, sb + S_VL + vbase + df * 16);
                mma_bf16(O[df], ph, vh);
                mma_bf16(O[df], ph, vl);
                mma_bf16(O[df], pl, vh);
            }
        }
    }

    // epilogue: normalize, split, write ctx
    const float inv0 = 1.0f / l0;
    const float inv1 = 1.0f / l1;
    const int row0 = qb * 64 + warp * 16 + r_in;
    #pragma unroll
    for (int df = 0; df < 8; df++) {
        const size_t col = hcol + df * 8 + c_in;
        uint32_t h0, lo0, h1, lo1;
        split2(O[df][0] * inv0, O[df][1] * inv0, h0, lo0);
        split2(O[df][2] * inv1, O[df][3] * inv1, h1, lo1);
        *(uint32_t*)(Chi + (rbase + row0) * H + col) = h0;
        *(uint32_t*)(Clo + (rbase + row0) * H + col) = lo0;
        *(uint32_t*)(Chi + (rbase + row0 + 8) * H + col) = h1;
        *(uint32_t*)(Clo + (rbase + row0 + 8) * H + col) = lo1;
    }
}

// ---------------------------------------------------------------------------
extern "C" void kernel_launch(void* const* d_in, const int* in_sizes, int n_in,
                              void* d_out, int out_size)
{
    const float* x  = (const float*)d_in[0];
    const float* Wq = (const float*)d_in[1];
    const float* bq = (const float*)d_in[2];
    const float* Wk = (const float*)d_in[3];
    const float* bk = (const float*)d_in[4];
    const float* Wv = (const float*)d_in[5];
    const float* bv = (const float*)d_in[6];
    const float* Wo = (const float*)d_in[7];
    const float* bo = (const float*)d_in[8];
    float* out = (float*)d_out;

    __nv_bfloat16 *qhi, *qlo, *khi, *klo, *vhi, *vlo, *chi, *clo;
    __nv_bfloat16 *xhi, *xlo, *wthi, *wtlo;
    cudaGetSymbolAddress((void**)&qhi, g_Qhi);
    cudaGetSymbolAddress((void**)&qlo, g_Qlo);
    cudaGetSymbolAddress((void**)&khi, g_Khi);
    cudaGetSymbolAddress((void**)&klo, g_Klo);
    cudaGetSymbolAddress((void**)&vhi, g_Vhi);
    cudaGetSymbolAddress((void**)&vlo, g_Vlo);
    cudaGetSymbolAddress((void**)&chi, g_chi);
    cudaGetSymbolAddress((void**)&clo, g_clo);
    cudaGetSymbolAddress((void**)&xhi, g_xhi);
    cudaGetSymbolAddress((void**)&xlo, g_xlo);
    cudaGetSymbolAddress((void**)&wthi, g_WThi);
    cudaGetSymbolAddress((void**)&wtlo, g_WTlo);

    const int nelem = MTOT * H;
    const size_t WSZ = (size_t)H * H;

    split_bf16<<<(nelem + 255) / 256, 256>>>(x, xhi, xlo, nelem);
    dim3 tgrid(H / 32, H / 32), tblk(32, 8);
    transpose_split<<<tgrid, tblk>>>(Wq, wthi + 0 * WSZ, wtlo + 0 * WSZ);
    transpose_split<<<tgrid, tblk>>>(Wk, wthi + 1 * WSZ, wtlo + 1 * WSZ);
    transpose_split<<<tgrid, tblk>>>(Wv, wthi + 2 * WSZ, wtlo + 2 * WSZ);
    transpose_split<<<tgrid, tblk>>>(Wo, wthi + 3 * WSZ, wtlo + 3 * WSZ);

    dim3 ggrid(H / 128, MTOT / 128);   // (8, 32)
    gemm_hmma_split<<<ggrid, 256>>>(xhi, xlo, wthi + 0 * WSZ, wtlo + 0 * WSZ,
                                    bq, QSCALE, qhi, qlo);
    gemm_hmma_split<<<ggrid, 256>>>(xhi, xlo, wthi + 1 * WSZ, wtlo + 1 * WSZ,
                                    bk, 1.0f, khi, klo);
    gemm_hmma_split<<<ggrid, 256>>>(xhi, xlo, wthi + 2 * WSZ, wtlo + 2 * WSZ,
                                    bv, 1.0f, vhi, vlo);

    dim3 agrid(SEQ / 64, BSZ * NH);    // (32, 32)
    attn_hmma<<<agrid, 128>>>(qhi, qlo, khi, klo, vhi, vlo, chi, clo);

    gemm_hmma_f32<<<ggrid, 256>>>(chi, clo, wthi + 3 * WSZ, wtlo + 3 * WSZ,
                                  bo, out);
}

// round 5
// speedup vs baseline: 2.6114x; 1.1464x over previous
#include <cuda_runtime.h>
#include <cuda_bf16.h>
#include <math.h>
#include <stdint.h>

#define H   1024
#define NH  16
#define HD  64
#define BSZ 2
#define SEQ 2048
#define MTOT (BSZ*SEQ)   // 4096 rows

// 0.125 (1/sqrt(HD)) * log2(e): folded into Q projection
#define QSCALE 0.18033688011112042f

// ---------------------------------------------------------------------------
// Scratch (allocation-free rule: __device__ globals)
// ---------------------------------------------------------------------------
__device__ __nv_bfloat16 g_Qhi[MTOT * H];
__device__ __nv_bfloat16 g_Qlo[MTOT * H];
__device__ __nv_bfloat16 g_Khi[MTOT * H];
__device__ __nv_bfloat16 g_Klo[MTOT * H];
__device__ __nv_bfloat16 g_Vhi[MTOT * H];
__device__ __nv_bfloat16 g_Vlo[MTOT * H];
__device__ __nv_bfloat16 g_chi[MTOT * H];
__device__ __nv_bfloat16 g_clo[MTOT * H];
__device__ __nv_bfloat16 g_xhi[MTOT * H];
__device__ __nv_bfloat16 g_xlo[MTOT * H];
__device__ __nv_bfloat16 g_WThi[4][H * H];   // W^T, bf16-hi, [N,K] K-major
__device__ __nv_bfloat16 g_WTlo[4][H * H];   // W^T, bf16-lo

// ---------------------------------------------------------------------------
// helpers
// ---------------------------------------------------------------------------
__device__ __forceinline__ uint32_t smem_u32(const void* p) {
    uint32_t a;
    asm("{ .reg .u64 t; cvta.to.shared.u64 t, %1; cvt.u32.u64 %0, t; }"
        : "=r"(a) : "l"(p));
    return a;
}
__device__ __forceinline__ void ldsm_x4(uint32_t* r, uint32_t addr) {
    asm volatile("ldmatrix.sync.aligned.m8n8.x4.shared.b16 {%0,%1,%2,%3}, [%4];"
                 : "=r"(r[0]), "=r"(r[1]), "=r"(r[2]), "=r"(r[3]) : "r"(addr));
}
__device__ __forceinline__ void ldsm_x2(uint32_t* r, uint32_t addr) {
    asm volatile("ldmatrix.sync.aligned.m8n8.x2.shared.b16 {%0,%1}, [%2];"
                 : "=r"(r[0]), "=r"(r[1]) : "r"(addr));
}
__device__ __forceinline__ void ldsm_x2t(uint32_t* r, uint32_t addr) {
    asm volatile("ldmatrix.sync.aligned.m8n8.x2.trans.shared.b16 {%0,%1}, [%2];"
                 : "=r"(r[0]), "=r"(r[1]) : "r"(addr));
}
__device__ __forceinline__ void mma_bf16(float* c, const uint32_t* a,
                                         const uint32_t* b) {
    asm volatile(
        "mma.sync.aligned.m16n8k16.row.col.f32.bf16.bf16.f32 "
        "{%0,%1,%2,%3}, {%4,%5,%6,%7}, {%8,%9}, {%0,%1,%2,%3};"
        : "+f"(c[0]), "+f"(c[1]), "+f"(c[2]), "+f"(c[3])
        : "r"(a[0]), "r"(a[1]), "r"(a[2]), "r"(a[3]), "r"(b[0]), "r"(b[1]));
}
__device__ __forceinline__ float exp2a(float x) {
    float y;
    asm("ex2.approx.f32 %0, %1;" : "=f"(y) : "f"(x));
    return y;
}
__device__ __forceinline__ void split2(float a, float b, uint32_t& hi, uint32_t& lo) {
    __nv_bfloat162 h = __floats2bfloat162_rn(a, b);
    float ra = a - __bfloat162float(h.x);
    float rb = b - __bfloat162float(h.y);
    __nv_bfloat162 l = __floats2bfloat162_rn(ra, rb);
    hi = *(uint32_t*)&h;
    lo = *(uint32_t*)&l;
}
__device__ __forceinline__ void cp16(uint32_t saddr, const void* g) {
    asm volatile("cp.async.cg.shared.global [%0], [%1], 16;"
                 :: "r"(saddr), "l"(g) : "memory");
}
__device__ __forceinline__ void cp_commit() {
    asm volatile("cp.async.commit_group;" ::: "memory");
}
template <int N>
__device__ __forceinline__ void cp_wait() {
    asm volatile("cp.async.wait_group %0;" :: "n"(N) : "memory");
}

// ---------------------------------------------------------------------------
// Prep
// ---------------------------------------------------------------------------
__global__ __launch_bounds__(256) void split_bf16(
    const float* __restrict__ src, __nv_bfloat16* __restrict__ hi,
    __nv_bfloat16* __restrict__ lo, int n)
{
    int i = blockIdx.x * 256 + threadIdx.x;
    if (i < n) {
        float v = src[i];
        __nv_bfloat16 h = __float2bfloat16(v);
        hi[i] = h;
        lo[i] = __float2bfloat16(v - __bfloat162float(h));
    }
}

__global__ __launch_bounds__(256) void transpose_split(
    const float* __restrict__ W, __nv_bfloat16* __restrict__ hi,
    __nv_bfloat16* __restrict__ lo)
{
    __shared__ float t[32][33];
    const int tx = threadIdx.x, ty = threadIdx.y;   // (32, 8)
    const int bx = blockIdx.x, by = blockIdx.y;
    #pragma unroll
    for (int i = 0; i < 4; i++)
        t[ty + 8 * i][tx] = W[(size_t)(by * 32 + ty + 8 * i) * H + bx * 32 + tx];
    __syncthreads();
    #pragma unroll
    for (int i = 0; i < 4; i++) {
        float v = t[tx][ty + 8 * i];
        int n = bx * 32 + ty + 8 * i;
        int k = by * 32 + tx;
        __nv_bfloat16 h = __float2bfloat16(v);
        hi[(size_t)n * H + k] = h;
        lo[(size_t)n * H + k] = __float2bfloat16(v - __bfloat162float(h));
    }
}

// ---------------------------------------------------------------------------
// HMMA split-bf16 GEMM, 2-stage cp.async pipeline.
// CTA 128x128, BK=32, 256 thr (8 warps 2x4), warp tile 64x32.
// ---------------------------------------------------------------------------
#define ROWB 80
#define TILEB (128 * ROWB)            // 10240
#define STAGEB (4 * TILEB)            // 40960
#define GEMM_SMEM (2 * STAGEB)        // 81920

template <bool SPLIT>
__device__ __forceinline__ void gemm_body(
    const __nv_bfloat16* __restrict__ Ahi, const __nv_bfloat16* __restrict__ Alo,
    const __nv_bfloat16* __restrict__ Bhi, const __nv_bfloat16* __restrict__ Blo,
    const float* __restrict__ bias, float scale,
    float* __restrict__ Cf, __nv_bfloat16* __restrict__ Chi,
    __nv_bfloat16* __restrict__ Clo)
{
    extern __shared__ __align__(16) char smem[];
    const uint32_t sb = smem_u32(smem);

    const int tid  = threadIdx.x;
    const int wid  = tid >> 5;
    const int lane = tid & 31;
    const int m0 = blockIdx.y * 128;
    const int n0 = blockIdx.x * 128;
    const int warp_m = wid >> 2;
    const int warp_n = wid & 3;

    float acc[4][4][4];
    #pragma unroll
    for (int i = 0; i < 4; i++)
        #pragma unroll
        for (int j = 0; j < 4; j++)
            #pragma unroll
            for (int r = 0; r < 4; r++) acc[i][j][r] = 0.0f;

    const uint32_t a_row = (lane & 15);
    const uint32_t a_koff = (lane >> 4) * 16;
    const uint32_t b_row = (lane & 7);
    const uint32_t b_koff = ((lane >> 3) & 1) * 16;

    const int g_row0 = tid >> 2;
    const int g_u4   = tid & 3;

    // stage loader: 8 cp.asyncs per thread
    auto load_stage = [&](int stage, int k0) {
        const uint32_t st = sb + stage * STAGEB;
        #pragma unroll
        for (int i = 0; i < 2; i++) {
            const int row = g_row0 + i * 64;
            const uint32_t so = (uint32_t)row * ROWB + g_u4 * 16;
            const size_t ga = (size_t)(m0 + row) * H + k0 + g_u4 * 8;
            const size_t gb = (size_t)(n0 + row) * H + k0 + g_u4 * 8;
            cp16(st + 0 * TILEB + so, Ahi + ga);
            cp16(st + 1 * TILEB + so, Alo + ga);
            cp16(st + 2 * TILEB + so, Bhi + gb);
            cp16(st + 3 * TILEB + so, Blo + gb);
        }
        cp_commit();
    };

    load_stage(0, 0);

    for (int kc = 0; kc < 32; kc++) {
        if (kc < 31) {
            load_stage((kc + 1) & 1, (kc + 1) * 32);
            cp_wait<1>();
        } else {
            cp_wait<0>();
        }
        __syncthreads();

        const uint32_t st = sb + (kc & 1) * STAGEB;
        const uint32_t S_AHI = st, S_ALO = st + TILEB,
                       S_BHI = st + 2 * TILEB, S_BLO = st + 3 * TILEB;

        #pragma unroll
        for (int ks = 0; ks < 2; ks++) {
            const uint32_t kb = ks * 32;
            uint32_t bh[4][2], bl[4][2];
            #pragma unroll
            for (int nf = 0; nf < 4; nf++) {
                const uint32_t boff =
                    (uint32_t)(warp_n * 32 + nf * 8 + b_row) * ROWB + kb + b_koff;
                ldsm_x2(bh[nf], S_BHI + boff);
                ldsm_x2(bl[nf], S_BLO + boff);
            }
            #pragma unroll
            for (int mf = 0; mf < 4; mf++) {
                const uint32_t aoff =
                    (uint32_t)(warp_m * 64 + mf * 16 + a_row) * ROWB + kb + a_koff;
                uint32_t ah[4], al[4];
                ldsm_x4(ah, S_AHI + aoff);
                ldsm_x4(al, S_ALO + aoff);
                #pragma unroll
                for (int nf = 0; nf < 4; nf++) {
                    mma_bf16(acc[mf][nf], ah, bh[nf]);
                    mma_bf16(acc[mf][nf], ah, bl[nf]);
                    mma_bf16(acc[mf][nf], al, bh[nf]);
                }
            }
        }
        __syncthreads();   // reads of this stage done before it is overwritten
    }

    const int r_in = lane >> 2;
    const int c_in = (lane & 3) * 2;
    #pragma unroll
    for (int nf = 0; nf < 4; nf++) {
        const int col = n0 + warp_n * 32 + nf * 8 + c_in;
        const float2 bv = *(const float2*)(bias + col);
        #pragma unroll
        for (int mf = 0; mf < 4; mf++) {
            const int row = m0 + warp_m * 64 + mf * 16 + r_in;
            float v00 = (acc[mf][nf][0] + bv.x) * scale;
            float v01 = (acc[mf][nf][1] + bv.y) * scale;
            float v10 = (acc[mf][nf][2] + bv.x) * scale;
            float v11 = (acc[mf][nf][3] + bv.y) * scale;
            if (SPLIT) {
                uint32_t h0, l0, h1, l1;
                split2(v00, v01, h0, l0);
                split2(v10, v11, h1, l1);
                *(uint32_t*)(Chi + (size_t)row * H + col) = h0;
                *(uint32_t*)(Clo + (size_t)row * H + col) = l0;
                *(uint32_t*)(Chi + (size_t)(row + 8) * H + col) = h1;
                *(uint32_t*)(Clo + (size_t)(row + 8) * H + col) = l1;
            } else {
                float2 o0 = { v00, v01 };
                float2 o1 = { v10, v11 };
                *(float2*)(Cf + (size_t)row * H + col) = o0;
                *(float2*)(Cf + (size_t)(row + 8) * H + col) = o1;
            }
        }
    }
}

__global__ __launch_bounds__(256) void gemm_hmma_f32(
    const __nv_bfloat16* __restrict__ Ahi, const __nv_bfloat16* __restrict__ Alo,
    const __nv_bfloat16* __restrict__ Bhi, const __nv_bfloat16* __restrict__ Blo,
    const float* __restrict__ bias, float* __restrict__ C)
{
    gemm_body<false>(Ahi, Alo, Bhi, Blo, bias, 1.0f, C, nullptr, nullptr);
}

__global__ __launch_bounds__(256) void gemm_hmma_split(
    const __nv_bfloat16* __restrict__ Ahi, const __nv_bfloat16* __restrict__ Alo,
    const __nv_bfloat16* __restrict__ Bhi, const __nv_bfloat16* __restrict__ Blo,
    const float* __restrict__ bias, float scale,
    __nv_bfloat16* __restrict__ Chi, __nv_bfloat16* __restrict__ Clo)
{
    gemm_body<true>(Ahi, Alo, Bhi, Blo, bias, scale, nullptr, Chi, Clo);
}

// ---------------------------------------------------------------------------
// HMMA flash attention, 2-stage cp.async KV pipeline.
// grid (SEQ/64, BSZ*NH), 128 threads (4 warps). Warp w owns q rows w*16..+15.
// ---------------------------------------------------------------------------
#define AROW 144
#define QTILE (64 * AROW)              // 9216
#define KVTILE (32 * AROW)             // 4608
#define KVSTAGE (4 * KVTILE)           // 18432
#define ATTN_SMEM (2 * QTILE + 2 * KVSTAGE)   // 55296

__global__ __launch_bounds__(128) void attn_hmma(
    const __nv_bfloat16* __restrict__ Qhi, const __nv_bfloat16* __restrict__ Qlo,
    const __nv_bfloat16* __restrict__ Khi, const __nv_bfloat16* __restrict__ Klo,
    const __nv_bfloat16* __restrict__ Vhi, const __nv_bfloat16* __restrict__ Vlo,
    __nv_bfloat16* __restrict__ Chi, __nv_bfloat16* __restrict__ Clo)
{
    extern __shared__ __align__(16) char smem[];
    const uint32_t sb = smem_u32(smem);
    const uint32_t S_QH = 0, S_QL = QTILE;

    const int tid  = threadIdx.x;
    const int warp = tid >> 5;
    const int lane = tid & 31;
    const int qb = blockIdx.x;
    const int b  = blockIdx.y / NH;
    const int h  = blockIdx.y % NH;
    const size_t hcol = (size_t)h * HD;
    const size_t rbase = (size_t)b * SEQ;

    // Load Q tile (64 x 64 bf16, hi+lo) via cp.async (group 0, waited below)
    #pragma unroll
    for (int t = 0; t < 4; t++) {
        const int idx = tid + t * 128;
        const int r = idx >> 3, c = idx & 7;
        const uint32_t so = (uint32_t)r * AROW + c * 16;
        const size_t g = (rbase + qb * 64 + r) * H + hcol + c * 8;
        cp16(sb + S_QH + so, Qhi + g);
        cp16(sb + S_QL + so, Qlo + g);
    }
    cp_commit();

    auto load_kv = [&](int stage, int kb) {
        const uint32_t st = sb + 2 * QTILE + stage * KVSTAGE;
        #pragma unroll
        for (int t = 0; t < 2; t++) {
            const int idx = tid + t * 128;
            const int r = idx >> 3, c = idx & 7;
            const uint32_t so = (uint32_t)r * AROW + c * 16;
            const size_t g = (rbase + kb * 32 + r) * H + hcol + c * 8;
            cp16(st + 0 * KVTILE + so, Khi + g);
            cp16(st + 1 * KVTILE + so, Klo + g);
            cp16(st + 2 * KVTILE + so, Vhi + g);
            cp16(st + 3 * KVTILE + so, Vlo + g);
        }
        cp_commit();
    };

    float O[8][4];
    #pragma unroll
    for (int d = 0; d < 8; d++)
        #pragma unroll
        for (int r = 0; r < 4; r++) O[d][r] = 0.0f;
    float m0 = -1e30f, m1 = -1e30f, l0 = 0.0f, l1 = 0.0f;

    const uint32_t a_base = S_QH + (uint32_t)(warp * 16 + (lane & 15)) * AROW
                          + (lane >> 4) * 16;
    const uint32_t al_base = a_base + QTILE;
    const uint32_t b_rowoff = (uint32_t)(lane & 7) * AROW + ((lane >> 3) & 1) * 16;
    const uint32_t v_laneoff = (uint32_t)(lane & 15) * AROW;

    const int r_in = lane >> 2;
    const int c_in = (lane & 3) * 2;

    const int nkb = 2 * qb + 2;
    load_kv(0, 0);

    for (int kb = 0; kb < nkb; kb++) {
        if (kb + 1 < nkb) {
            load_kv((kb + 1) & 1, kb + 1);
            cp_wait<1>();
        } else {
            cp_wait<0>();
        }
        __syncthreads();

        const uint32_t st = sb + 2 * QTILE + (kb & 1) * KVSTAGE;
        const uint32_t S_KH = st, S_KL = st + KVTILE,
                       S_VH = st + 2 * KVTILE, S_VL = st + 3 * KVTILE;

        // S = Q K^T
        float s[4][4];
        #pragma unroll
        for (int nf = 0; nf < 4; nf++)
            #pragma unroll
            for (int r = 0; r < 4; r++) s[nf][r] = 0.0f;

        #pragma unroll
        for (int ks = 0; ks < 4; ks++) {
            uint32_t ah[4], al[4];
            ldsm_x4(ah, sb + a_base + ks * 32);
            ldsm_x4(al, sb + al_base + ks * 32);
            #pragma unroll
            for (int nf = 0; nf < 4; nf++) {
                uint32_t bh[2], bl[2];
                const uint32_t bo = (uint32_t)(nf * 8) * AROW + b_rowoff + ks * 32;
                ldsm_x2(bh, S_KH + bo);
                ldsm_x2(bl, S_KL + bo);
                mma_bf16(s[nf], ah, bh);
                mma_bf16(s[nf], ah, bl);
                mma_bf16(s[nf], al, bh);
            }
        }

        if (kb >= 2 * qb) {
            const int row0 = qb * 64 + warp * 16 + r_in;
            const int row1 = row0 + 8;
            #pragma unroll
            for (int nf = 0; nf < 4; nf++) {
                const int cg = kb * 32 + nf * 8 + c_in;
                if (cg > row0)     s[nf][0] = -1e30f;
                if (cg + 1 > row0) s[nf][1] = -1e30f;
                if (cg > row1)     s[nf][2] = -1e30f;
                if (cg + 1 > row1) s[nf][3] = -1e30f;
            }
        }

        // online softmax
        float rmax0 = -1e30f, rmax1 = -1e30f;
        #pragma unroll
        for (int nf = 0; nf < 4; nf++) {
            rmax0 = fmaxf(rmax0, fmaxf(s[nf][0], s[nf][1]));
            rmax1 = fmaxf(rmax1, fmaxf(s[nf][2], s[nf][3]));
        }
        rmax0 = fmaxf(rmax0, __shfl_xor_sync(0xffffffffu, rmax0, 1));
        rmax0 = fmaxf(rmax0, __shfl_xor_sync(0xffffffffu, rmax0, 2));
        rmax1 = fmaxf(rmax1, __shfl_xor_sync(0xffffffffu, rmax1, 1));
        rmax1 = fmaxf(rmax1, __shfl_xor_sync(0xffffffffu, rmax1, 2));
        const float mn0 = fmaxf(m0, rmax0);
        const float mn1 = fmaxf(m1, rmax1);
        const float sc0 = exp2a(m0 - mn0);
        const float sc1 = exp2a(m1 - mn1);

        float rs0 = 0.0f, rs1 = 0.0f;
        uint32_t phi01[4], phi23[4], plo01[4], plo23[4];
        #pragma unroll
        for (int nf = 0; nf < 4; nf++) {
            float p00 = exp2a(s[nf][0] - mn0);
            float p01 = exp2a(s[nf][1] - mn0);
            float p10 = exp2a(s[nf][2] - mn1);
            float p11 = exp2a(s[nf][3] - mn1);
            rs0 += p00 + p01;
            rs1 += p10 + p11;
            split2(p00, p01, phi01[nf], plo01[nf]);
            split2(p10, p11, phi23[nf], plo23[nf]);
        }
        rs0 += __shfl_xor_sync(0xffffffffu, rs0, 1);
        rs0 += __shfl_xor_sync(0xffffffffu, rs0, 2);
        rs1 += __shfl_xor_sync(0xffffffffu, rs1, 1);
        rs1 += __shfl_xor_sync(0xffffffffu, rs1, 2);
        l0 = l0 * sc0 + rs0;
        l1 = l1 * sc1 + rs1;
        m0 = mn0; m1 = mn1;
        #pragma unroll
        for (int d = 0; d < 8; d++) {
            O[d][0] *= sc0; O[d][1] *= sc0;
            O[d][2] *= sc1; O[d][3] *= sc1;
        }

        // O += P V
        #pragma unroll
        for (int ksj = 0; ksj < 2; ksj++) {
            const uint32_t ph[4] = { phi01[2*ksj], phi23[2*ksj],
                                     phi01[2*ksj+1], phi23[2*ksj+1] };
            const uint32_t pl[4] = { plo01[2*ksj], plo23[2*ksj],
                                     plo01[2*ksj+1], plo23[2*ksj+1] };
            const uint32_t vbase = (uint32_t)(ksj * 16) * AROW + v_laneoff;
            #pragma unroll
            for (int df = 0; df < 8; df++) {
                uint32_t vh[2], vl[2];
                ldsm_x2t(vh, S_VH + vbase + df * 16);
                ldsm_x2t(vl, S_VL + vbase + df * 16);
                mma_bf16(O[df], ph, vh);
                mma_bf16(O[df], ph, vl);
                mma_bf16(O[df], pl, vh);
            }
        }
        __syncthreads();   // stage reads done before overwrite by next prefetch
    }

    const float inv0 = 1.0f / l0;
    const float inv1 = 1.0f / l1;
    const int row0 = qb * 64 + warp * 16 + r_in;
    #pragma unroll
    for (int df = 0; df < 8; df++) {
        const size_t col = hcol + df * 8 + c_in;
        uint32_t h0, lo0, h1, lo1;
        split2(O[df][0] * inv0, O[df][1] * inv0, h0, lo0);
        split2(O[df][2] * inv1, O[df][3] * inv1, h1, lo1);
        *(uint32_t*)(Chi + (rbase + row0) * H + col) = h0;
        *(uint32_t*)(Clo + (rbase + row0) * H + col) = lo0;
        *(uint32_t*)(Chi + (rbase + row0 + 8) * H + col) = h1;
        *(uint32_t*)(Clo + (rbase + row0 + 8) * H + col) = lo1;
    }
}

// ---------------------------------------------------------------------------
extern "C" void kernel_launch(void* const* d_in, const int* in_sizes, int n_in,
                              void* d_out, int out_size)
{
    const float* x  = (const float*)d_in[0];
    const float* Wq = (const float*)d_in[1];
    const float* bq = (const float*)d_in[2];
    const float* Wk = (const float*)d_in[3];
    const float* bk = (const float*)d_in[4];
    const float* Wv = (const float*)d_in[5];
    const float* bv = (const float*)d_in[6];
    const float* Wo = (const float*)d_in[7];
    const float* bo = (const float*)d_in[8];
    float* out = (float*)d_out;

    cudaFuncSetAttribute(gemm_hmma_split,
                         cudaFuncAttributeMaxDynamicSharedMemorySize, GEMM_SMEM);
    cudaFuncSetAttribute(gemm_hmma_f32,
                         cudaFuncAttributeMaxDynamicSharedMemorySize, GEMM_SMEM);
    cudaFuncSetAttribute(attn_hmma,
                         cudaFuncAttributeMaxDynamicSharedMemorySize, ATTN_SMEM);

    __nv_bfloat16 *qhi, *qlo, *khi, *klo, *vhi, *vlo, *chi, *clo;
    __nv_bfloat16 *xhi, *xlo, *wthi, *wtlo;
    cudaGetSymbolAddress((void**)&qhi, g_Qhi);
    cudaGetSymbolAddress((void**)&qlo, g_Qlo);
    cudaGetSymbolAddress((void**)&khi, g_Khi);
    cudaGetSymbolAddress((void**)&klo, g_Klo);
    cudaGetSymbolAddress((void**)&vhi, g_Vhi);
    cudaGetSymbolAddress((void**)&vlo, g_Vlo);
    cudaGetSymbolAddress((void**)&chi, g_chi);
    cudaGetSymbolAddress((void**)&clo, g_clo);
    cudaGetSymbolAddress((void**)&xhi, g_xhi);
    cudaGetSymbolAddress((void**)&xlo, g_xlo);
    cudaGetSymbolAddress((void**)&wthi, g_WThi);
    cudaGetSymbolAddress((void**)&wtlo, g_WTlo);

    const int nelem = MTOT * H;
    const size_t WSZ = (size_t)H * H;

    split_bf16<<<(nelem + 255) / 256, 256>>>(x, xhi, xlo, nelem);
    dim3 tgrid(H / 32, H / 32), tblk(32, 8);
    transpose_split<<<tgrid, tblk>>>(Wq, wthi + 0 * WSZ, wtlo + 0 * WSZ);
    transpose_split<<<tgrid, tblk>>>(Wk, wthi + 1 * WSZ, wtlo + 1 * WSZ);
    transpose_split<<<tgrid, tblk>>>(Wv, wthi + 2 * WSZ, wtlo + 2 * WSZ);
    transpose_split<<<tgrid, tblk>>>(Wo, wthi + 3 * WSZ, wtlo + 3 * WSZ);

    dim3 ggrid(H / 128, MTOT / 128);   // (8, 32)
    gemm_hmma_split<<<ggrid, 256, GEMM_SMEM>>>(xhi, xlo,
        wthi + 0 * WSZ, wtlo + 0 * WSZ, bq, QSCALE, qhi, qlo);
    gemm_hmma_split<<<ggrid, 256, GEMM_SMEM>>>(xhi, xlo,
        wthi + 1 * WSZ, wtlo + 1 * WSZ, bk, 1.0f, khi, klo);
    gemm_hmma_split<<<ggrid, 256, GEMM_SMEM>>>(xhi, xlo,
        wthi + 2 * WSZ, wtlo + 2 * WSZ, bv, 1.0f, vhi, vlo);

    dim3 agrid(SEQ / 64, BSZ * NH);    // (32, 32)
    attn_hmma<<<agrid, 128, ATTN_SMEM>>>(qhi, qlo, khi, klo, vhi, vlo, chi, clo);

    gemm_hmma_f32<<<ggrid, 256, GEMM_SMEM>>>(chi, clo,
        wthi + 3 * WSZ, wtlo + 3 * WSZ, bo, out);
}

// round 6
// speedup vs baseline: 2.9255x; 1.1203x over previous
#include <cuda_runtime.h>
#include <cuda_bf16.h>
#include <math.h>
#include <stdint.h>

#define H   1024
#define NH  16
#define HD  64
#define BSZ 2
#define SEQ 2048
#define MTOT (BSZ*SEQ)   // 4096 rows

// 0.125 (1/sqrt(HD)) * log2(e): folded into Q projection
#define QSCALE 0.18033688011112042f

// ---------------------------------------------------------------------------
// Scratch (allocation-free rule: __device__ globals)
// ---------------------------------------------------------------------------
__device__ __nv_bfloat16 g_Qhi[MTOT * H];
__device__ __nv_bfloat16 g_Qlo[MTOT * H];
__device__ __nv_bfloat16 g_Khi[MTOT * H];
__device__ __nv_bfloat16 g_Klo[MTOT * H];
__device__ __nv_bfloat16 g_Vhi[MTOT * H];
__device__ __nv_bfloat16 g_Vlo[MTOT * H];
__device__ __nv_bfloat16 g_chi[MTOT * H];
__device__ __nv_bfloat16 g_clo[MTOT * H];
__device__ __nv_bfloat16 g_xhi[MTOT * H];
__device__ __nv_bfloat16 g_xlo[MTOT * H];
__device__ __nv_bfloat16 g_WThi[4][H * H];   // W^T, bf16-hi, [N,K] K-major
__device__ __nv_bfloat16 g_WTlo[4][H * H];   // W^T, bf16-lo

// ---------------------------------------------------------------------------
// helpers
// ---------------------------------------------------------------------------
__device__ __forceinline__ uint32_t smem_u32(const void* p) {
    uint32_t a;
    asm("{ .reg .u64 t; cvta.to.shared.u64 t, %1; cvt.u32.u64 %0, t; }"
        : "=r"(a) : "l"(p));
    return a;
}
__device__ __forceinline__ void ldsm_x4(uint32_t* r, uint32_t addr) {
    asm volatile("ldmatrix.sync.aligned.m8n8.x4.shared.b16 {%0,%1,%2,%3}, [%4];"
                 : "=r"(r[0]), "=r"(r[1]), "=r"(r[2]), "=r"(r[3]) : "r"(addr));
}
__device__ __forceinline__ void ldsm_x2(uint32_t* r, uint32_t addr) {
    asm volatile("ldmatrix.sync.aligned.m8n8.x2.shared.b16 {%0,%1}, [%2];"
                 : "=r"(r[0]), "=r"(r[1]) : "r"(addr));
}
__device__ __forceinline__ void ldsm_x2t(uint32_t* r, uint32_t addr) {
    asm volatile("ldmatrix.sync.aligned.m8n8.x2.trans.shared.b16 {%0,%1}, [%2];"
                 : "=r"(r[0]), "=r"(r[1]) : "r"(addr));
}
__device__ __forceinline__ void mma_bf16(float* c, const uint32_t* a,
                                         const uint32_t* b) {
    asm volatile(
        "mma.sync.aligned.m16n8k16.row.col.f32.bf16.bf16.f32 "
        "{%0,%1,%2,%3}, {%4,%5,%6,%7}, {%8,%9}, {%0,%1,%2,%3};"
        : "+f"(c[0]), "+f"(c[1]), "+f"(c[2]), "+f"(c[3])
        : "r"(a[0]), "r"(a[1]), "r"(a[2]), "r"(a[3]), "r"(b[0]), "r"(b[1]));
}
__device__ __forceinline__ float exp2a(float x) {
    float y;
    asm("ex2.approx.f32 %0, %1;" : "=f"(y) : "f"(x));
    return y;
}
__device__ __forceinline__ void split2(float a, float b, uint32_t& hi, uint32_t& lo) {
    __nv_bfloat162 h = __floats2bfloat162_rn(a, b);
    float ra = a - __bfloat162float(h.x);
    float rb = b - __bfloat162float(h.y);
    __nv_bfloat162 l = __floats2bfloat162_rn(ra, rb);
    hi = *(uint32_t*)&h;
    lo = *(uint32_t*)&l;
}
__device__ __forceinline__ void cp16(uint32_t saddr, const void* g) {
    asm volatile("cp.async.cg.shared.global [%0], [%1], 16;"
                 :: "r"(saddr), "l"(g) : "memory");
}
__device__ __forceinline__ void cp_commit() {
    asm volatile("cp.async.commit_group;" ::: "memory");
}
template <int N>
__device__ __forceinline__ void cp_wait() {
    asm volatile("cp.async.wait_group %0;" :: "n"(N) : "memory");
}

// ---------------------------------------------------------------------------
// Prep
// ---------------------------------------------------------------------------
__global__ __launch_bounds__(256) void split_bf16_v4(
    const float* __restrict__ src, __nv_bfloat16* __restrict__ hi,
    __nv_bfloat16* __restrict__ lo, int n4)
{
    int i = blockIdx.x * 256 + threadIdx.x;
    if (i < n4) {
        float4 v = ((const float4*)src)[i];
        __nv_bfloat162 h0 = __floats2bfloat162_rn(v.x, v.y);
        __nv_bfloat162 h1 = __floats2bfloat162_rn(v.z, v.w);
        __nv_bfloat162 l0 = __floats2bfloat162_rn(v.x - __bfloat162float(h0.x),
                                                  v.y - __bfloat162float(h0.y));
        __nv_bfloat162 l1 = __floats2bfloat162_rn(v.z - __bfloat162float(h1.x),
                                                  v.w - __bfloat162float(h1.y));
        uint2 ho = { *(uint32_t*)&h0, *(uint32_t*)&h1 };
        uint2 loo = { *(uint32_t*)&l0, *(uint32_t*)&l1 };
        ((uint2*)hi)[i] = ho;
        ((uint2*)lo)[i] = loo;
    }
}

// All 4 weight transposes in one launch (blockIdx.z selects the matrix)
__global__ __launch_bounds__(256) void transpose_split4(
    const float* __restrict__ W0, const float* __restrict__ W1,
    const float* __restrict__ W2, const float* __restrict__ W3,
    __nv_bfloat16* __restrict__ hi, __nv_bfloat16* __restrict__ lo)
{
    __shared__ float t[32][33];
    const int z = blockIdx.z;
    const float* W = (z == 0) ? W0 : (z == 1) ? W1 : (z == 2) ? W2 : W3;
    const size_t off = (size_t)z * H * H;
    const int tx = threadIdx.x, ty = threadIdx.y;   // (32, 8)
    const int bx = blockIdx.x, by = blockIdx.y;
    #pragma unroll
    for (int i = 0; i < 4; i++)
        t[ty + 8 * i][tx] = W[(size_t)(by * 32 + ty + 8 * i) * H + bx * 32 + tx];
    __syncthreads();
    #pragma unroll
    for (int i = 0; i < 4; i++) {
        float v = t[tx][ty + 8 * i];
        int n = bx * 32 + ty + 8 * i;
        int k = by * 32 + tx;
        __nv_bfloat16 h = __float2bfloat16(v);
        hi[off + (size_t)n * H + k] = h;
        lo[off + (size_t)n * H + k] = __float2bfloat16(v - __bfloat162float(h));
    }
}

// ---------------------------------------------------------------------------
// HMMA split-bf16 GEMM, 2-stage cp.async pipeline, ONE barrier per k-iter.
// CTA 128x128, BK=32, 256 thr (8 warps 2x4), warp tile 64x32.
// ---------------------------------------------------------------------------
#define ROWB 80
#define TILEB (128 * ROWB)            // 10240
#define STAGEB (4 * TILEB)            // 40960
#define GEMM_SMEM (2 * STAGEB)        // 81920

template <bool SPLIT>
__device__ __forceinline__ void gemm_body(
    const __nv_bfloat16* __restrict__ Ahi, const __nv_bfloat16* __restrict__ Alo,
    const __nv_bfloat16* __restrict__ Bhi, const __nv_bfloat16* __restrict__ Blo,
    const float* __restrict__ bias, float scale,
    float* __restrict__ Cf, __nv_bfloat16* __restrict__ Chi,
    __nv_bfloat16* __restrict__ Clo)
{
    extern __shared__ __align__(16) char smem[];
    const uint32_t sb = smem_u32(smem);

    const int tid  = threadIdx.x;
    const int wid  = tid >> 5;
    const int lane = tid & 31;
    const int m0 = blockIdx.y * 128;
    const int n0 = blockIdx.x * 128;
    const int warp_m = wid >> 2;
    const int warp_n = wid & 3;

    float acc[4][4][4];
    #pragma unroll
    for (int i = 0; i < 4; i++)
        #pragma unroll
        for (int j = 0; j < 4; j++)
            #pragma unroll
            for (int r = 0; r < 4; r++) acc[i][j][r] = 0.0f;

    const uint32_t a_row = (lane & 15);
    const uint32_t a_koff = (lane >> 4) * 16;
    const uint32_t b_row = (lane & 7);
    const uint32_t b_koff = ((lane >> 3) & 1) * 16;

    const int g_row0 = tid >> 2;
    const int g_u4   = tid & 3;

    auto load_stage = [&](int stage, int k0) {
        const uint32_t st = sb + stage * STAGEB;
        #pragma unroll
        for (int i = 0; i < 2; i++) {
            const int row = g_row0 + i * 64;
            const uint32_t so = (uint32_t)row * ROWB + g_u4 * 16;
            const size_t ga = (size_t)(m0 + row) * H + k0 + g_u4 * 8;
            const size_t gb = (size_t)(n0 + row) * H + k0 + g_u4 * 8;
            cp16(st + 0 * TILEB + so, Ahi + ga);
            cp16(st + 1 * TILEB + so, Alo + ga);
            cp16(st + 2 * TILEB + so, Bhi + gb);
            cp16(st + 3 * TILEB + so, Blo + gb);
        }
        cp_commit();
    };

    load_stage(0, 0);

    for (int kc = 0; kc < 32; kc++) {
        cp_wait<0>();
        __syncthreads();   // data visible; also: everyone finished iter kc-1
        if (kc < 31) load_stage((kc + 1) & 1, (kc + 1) * 32);

        const uint32_t st = sb + (kc & 1) * STAGEB;
        const uint32_t S_AHI = st, S_ALO = st + TILEB,
                       S_BHI = st + 2 * TILEB, S_BLO = st + 3 * TILEB;

        #pragma unroll
        for (int ks = 0; ks < 2; ks++) {
            const uint32_t kb = ks * 32;
            uint32_t bh[4][2], bl[4][2];
            #pragma unroll
            for (int nf = 0; nf < 4; nf++) {
                const uint32_t boff =
                    (uint32_t)(warp_n * 32 + nf * 8 + b_row) * ROWB + kb + b_koff;
                ldsm_x2(bh[nf], S_BHI + boff);
                ldsm_x2(bl[nf], S_BLO + boff);
            }
            #pragma unroll
            for (int mf = 0; mf < 4; mf++) {
                const uint32_t aoff =
                    (uint32_t)(warp_m * 64 + mf * 16 + a_row) * ROWB + kb + a_koff;
                uint32_t ah[4], al[4];
                ldsm_x4(ah, S_AHI + aoff);
                ldsm_x4(al, S_ALO + aoff);
                #pragma unroll
                for (int nf = 0; nf < 4; nf++) {
                    mma_bf16(acc[mf][nf], ah, bh[nf]);
                    mma_bf16(acc[mf][nf], ah, bl[nf]);
                    mma_bf16(acc[mf][nf], al, bh[nf]);
                }
            }
        }
    }

    const int r_in = lane >> 2;
    const int c_in = (lane & 3) * 2;
    #pragma unroll
    for (int nf = 0; nf < 4; nf++) {
        const int col = n0 + warp_n * 32 + nf * 8 + c_in;
        const float2 bv = *(const float2*)(bias + col);
        #pragma unroll
        for (int mf = 0; mf < 4; mf++) {
            const int row = m0 + warp_m * 64 + mf * 16 + r_in;
            float v00 = (acc[mf][nf][0] + bv.x) * scale;
            float v01 = (acc[mf][nf][1] + bv.y) * scale;
            float v10 = (acc[mf][nf][2] + bv.x) * scale;
            float v11 = (acc[mf][nf][3] + bv.y) * scale;
            if (SPLIT) {
                uint32_t h0, l0, h1, l1;
                split2(v00, v01, h0, l0);
                split2(v10, v11, h1, l1);
                *(uint32_t*)(Chi + (size_t)row * H + col) = h0;
                *(uint32_t*)(Clo + (size_t)row * H + col) = l0;
                *(uint32_t*)(Chi + (size_t)(row + 8) * H + col) = h1;
                *(uint32_t*)(Clo + (size_t)(row + 8) * H + col) = l1;
            } else {
                float2 o0 = { v00, v01 };
                float2 o1 = { v10, v11 };
                *(float2*)(Cf + (size_t)row * H + col) = o0;
                *(float2*)(Cf + (size_t)(row + 8) * H + col) = o1;
            }
        }
    }
}

__global__ __launch_bounds__(256, 2) void gemm_hmma_f32(
    const __nv_bfloat16* __restrict__ Ahi, const __nv_bfloat16* __restrict__ Alo,
    const __nv_bfloat16* __restrict__ Bhi, const __nv_bfloat16* __restrict__ Blo,
    const float* __restrict__ bias, float* __restrict__ C)
{
    gemm_body<false>(Ahi, Alo, Bhi, Blo, bias, 1.0f, C, nullptr, nullptr);
}

__global__ __launch_bounds__(256, 2) void gemm_hmma_split(
    const __nv_bfloat16* __restrict__ Ahi, const __nv_bfloat16* __restrict__ Alo,
    const __nv_bfloat16* __restrict__ Bhi, const __nv_bfloat16* __restrict__ Blo,
    const float* __restrict__ bias, float scale,
    __nv_bfloat16* __restrict__ Chi, __nv_bfloat16* __restrict__ Clo)
{
    gemm_body<true>(Ahi, Alo, Bhi, Blo, bias, scale, nullptr, Chi, Clo);
}

// ---------------------------------------------------------------------------
// HMMA flash attention, Bc=64 KV tiles, 2-stage cp.async, one barrier/iter.
// grid (SEQ/64, BSZ*NH), 128 threads (4 warps). Warp w owns q rows w*16..+15.
// ---------------------------------------------------------------------------
#define AROW 144
#define QTILE (64 * AROW)              // 9216
#define KVTILE (64 * AROW)             // 9216
#define KVSTAGE (4 * KVTILE)           // 36864
#define ATTN_SMEM (2 * QTILE + 2 * KVSTAGE)   // 92160

__global__ __launch_bounds__(128) void attn_hmma(
    const __nv_bfloat16* __restrict__ Qhi, const __nv_bfloat16* __restrict__ Qlo,
    const __nv_bfloat16* __restrict__ Khi, const __nv_bfloat16* __restrict__ Klo,
    const __nv_bfloat16* __restrict__ Vhi, const __nv_bfloat16* __restrict__ Vlo,
    __nv_bfloat16* __restrict__ Chi, __nv_bfloat16* __restrict__ Clo)
{
    extern __shared__ __align__(16) char smem[];
    const uint32_t sb = smem_u32(smem);
    const uint32_t S_QH = 0, S_QL = QTILE;

    const int tid  = threadIdx.x;
    const int warp = tid >> 5;
    const int lane = tid & 31;
    const int qb = blockIdx.x;
    const int b  = blockIdx.y / NH;
    const int h  = blockIdx.y % NH;
    const size_t hcol = (size_t)h * HD;
    const size_t rbase = (size_t)b * SEQ;

    // Q tile (64 x 64 bf16, hi+lo) via cp.async
    #pragma unroll
    for (int t = 0; t < 4; t++) {
        const int idx = tid + t * 128;
        const int r = idx >> 3, c = idx & 7;
        const uint32_t so = (uint32_t)r * AROW + c * 16;
        const size_t g = (rbase + qb * 64 + r) * H + hcol + c * 8;
        cp16(sb + S_QH + so, Qhi + g);
        cp16(sb + S_QL + so, Qlo + g);
    }
    cp_commit();

    auto load_kv = [&](int stage, int kb) {
        const uint32_t st = sb + 2 * QTILE + stage * KVSTAGE;
        #pragma unroll
        for (int t = 0; t < 4; t++) {
            const int idx = tid + t * 128;
            const int r = idx >> 3, c = idx & 7;
            const uint32_t so = (uint32_t)r * AROW + c * 16;
            const size_t g = (rbase + kb * 64 + r) * H + hcol + c * 8;
            cp16(st + 0 * KVTILE + so, Khi + g);
            cp16(st + 1 * KVTILE + so, Klo + g);
            cp16(st + 2 * KVTILE + so, Vhi + g);
            cp16(st + 3 * KVTILE + so, Vlo + g);
        }
        cp_commit();
    };

    float O[8][4];
    #pragma unroll
    for (int d = 0; d < 8; d++)
        #pragma unroll
        for (int r = 0; r < 4; r++) O[d][r] = 0.0f;
    float m0 = -1e30f, m1 = -1e30f, l0 = 0.0f, l1 = 0.0f;

    const uint32_t a_base = S_QH + (uint32_t)(warp * 16 + (lane & 15)) * AROW
                          + (lane >> 4) * 16;
    const uint32_t al_base = a_base + QTILE;
    const uint32_t b_rowoff = (uint32_t)(lane & 7) * AROW + ((lane >> 3) & 1) * 16;
    const uint32_t v_laneoff = (uint32_t)(lane & 15) * AROW;

    const int r_in = lane >> 2;
    const int c_in = (lane & 3) * 2;

    const int nkb = qb + 1;
    load_kv(0, 0);

    for (int kb = 0; kb < nkb; kb++) {
        cp_wait<0>();
        __syncthreads();
        if (kb + 1 < nkb) load_kv((kb + 1) & 1, kb + 1);

        const uint32_t st = sb + 2 * QTILE + (kb & 1) * KVSTAGE;
        const uint32_t S_KH = st, S_KL = st + KVTILE,
                       S_VH = st + 2 * KVTILE, S_VL = st + 3 * KVTILE;

        // S = Q K^T (64 x 64 per warp-row group)
        float s[8][4];
        #pragma unroll
        for (int nf = 0; nf < 8; nf++)
            #pragma unroll
            for (int r = 0; r < 4; r++) s[nf][r] = 0.0f;

        #pragma unroll
        for (int ks = 0; ks < 4; ks++) {
            uint32_t ah[4], al[4];
            ldsm_x4(ah, sb + a_base + ks * 32);
            ldsm_x4(al, sb + al_base + ks * 32);
            #pragma unroll
            for (int nf = 0; nf < 8; nf++) {
                uint32_t bh[2], bl[2];
                const uint32_t bo = (uint32_t)(nf * 8) * AROW + b_rowoff + ks * 32;
                ldsm_x2(bh, S_KH + bo);
                ldsm_x2(bl, S_KL + bo);
                mma_bf16(s[nf], ah, bh);
                mma_bf16(s[nf], ah, bl);
                mma_bf16(s[nf], al, bh);
            }
        }

        if (kb == qb) {   // diagonal tile: causal mask
            const int row0 = qb * 64 + warp * 16 + r_in;
            const int row1 = row0 + 8;
            #pragma unroll
            for (int nf = 0; nf < 8; nf++) {
                const int cg = kb * 64 + nf * 8 + c_in;
                if (cg > row0)     s[nf][0] = -1e30f;
                if (cg + 1 > row0) s[nf][1] = -1e30f;
                if (cg > row1)     s[nf][2] = -1e30f;
                if (cg + 1 > row1) s[nf][3] = -1e30f;
            }
        }

        // online softmax
        float rmax0 = -1e30f, rmax1 = -1e30f;
        #pragma unroll
        for (int nf = 0; nf < 8; nf++) {
            rmax0 = fmaxf(rmax0, fmaxf(s[nf][0], s[nf][1]));
            rmax1 = fmaxf(rmax1, fmaxf(s[nf][2], s[nf][3]));
        }
        rmax0 = fmaxf(rmax0, __shfl_xor_sync(0xffffffffu, rmax0, 1));
        rmax0 = fmaxf(rmax0, __shfl_xor_sync(0xffffffffu, rmax0, 2));
        rmax1 = fmaxf(rmax1, __shfl_xor_sync(0xffffffffu, rmax1, 1));
        rmax1 = fmaxf(rmax1, __shfl_xor_sync(0xffffffffu, rmax1, 2));
        const float mn0 = fmaxf(m0, rmax0);
        const float mn1 = fmaxf(m1, rmax1);
        const float sc0 = exp2a(m0 - mn0);
        const float sc1 = exp2a(m1 - mn1);

        float rs0 = 0.0f, rs1 = 0.0f;
        uint32_t phi01[8], phi23[8], plo01[8], plo23[8];
        #pragma unroll
        for (int nf = 0; nf < 8; nf++) {
            float p00 = exp2a(s[nf][0] - mn0);
            float p01 = exp2a(s[nf][1] - mn0);
            float p10 = exp2a(s[nf][2] - mn1);
            float p11 = exp2a(s[nf][3] - mn1);
            rs0 += p00 + p01;
            rs1 += p10 + p11;
            split2(p00, p01, phi01[nf], plo01[nf]);
            split2(p10, p11, phi23[nf], plo23[nf]);
        }
        rs0 += __shfl_xor_sync(0xffffffffu, rs0, 1);
        rs0 += __shfl_xor_sync(0xffffffffu, rs0, 2);
        rs1 += __shfl_xor_sync(0xffffffffu, rs1, 1);
        rs1 += __shfl_xor_sync(0xffffffffu, rs1, 2);
        l0 = l0 * sc0 + rs0;
        l1 = l1 * sc1 + rs1;
        m0 = mn0; m1 = mn1;
        #pragma unroll
        for (int d = 0; d < 8; d++) {
            O[d][0] *= sc0; O[d][1] *= sc0;
            O[d][2] *= sc1; O[d][3] *= sc1;
        }

        // O += P V  (4 k-steps of 16 over the 64 keys)
        #pragma unroll
        for (int ksj = 0; ksj < 4; ksj++) {
            const uint32_t ph[4] = { phi01[2*ksj], phi23[2*ksj],
                                     phi01[2*ksj+1], phi23[2*ksj+1] };
            const uint32_t pl[4] = { plo01[2*ksj], plo23[2*ksj],
                                     plo01[2*ksj+1], plo23[2*ksj+1] };
            const uint32_t vbase = (uint32_t)(ksj * 16) * AROW + v_laneoff;
            #pragma unroll
            for (int df = 0; df < 8; df++) {
                uint32_t vh[2], vl[2];
                ldsm_x2t(vh, S_VH + vbase + df * 16);
                ldsm_x2t(vl, S_VL + vbase + df * 16);
                mma_bf16(O[df], ph, vh);
                mma_bf16(O[df], ph, vl);
                mma_bf16(O[df], pl, vh);
            }
        }
    }

    const float inv0 = 1.0f / l0;
    const float inv1 = 1.0f / l1;
    const int row0 = qb * 64 + warp * 16 + r_in;
    #pragma unroll
    for (int df = 0; df < 8; df++) {
        const size_t col = hcol + df * 8 + c_in;
        uint32_t h0, lo0, h1, lo1;
        split2(O[df][0] * inv0, O[df][1] * inv0, h0, lo0);
        split2(O[df][2] * inv1, O[df][3] * inv1, h1, lo1);
        *(uint32_t*)(Chi + (rbase + row0) * H + col) = h0;
        *(uint32_t*)(Clo + (rbase + row0) * H + col) = lo0;
        *(uint32_t*)(Chi + (rbase + row0 + 8) * H + col) = h1;
        *(uint32_t*)(Clo + (rbase + row0 + 8) * H + col) = lo1;
    }
}

// ---------------------------------------------------------------------------
extern "C" void kernel_launch(void* const* d_in, const int* in_sizes, int n_in,
                              void* d_out, int out_size)
{
    const float* x  = (const float*)d_in[0];
    const float* Wq = (const float*)d_in[1];
    const float* bq = (const float*)d_in[2];
    const float* Wk = (const float*)d_in[3];
    const float* bk = (const float*)d_in[4];
    const float* Wv = (const float*)d_in[5];
    const float* bv = (const float*)d_in[6];
    const float* Wo = (const float*)d_in[7];
    const float* bo = (const float*)d_in[8];
    float* out = (float*)d_out;

    cudaFuncSetAttribute(gemm_hmma_split,
                         cudaFuncAttributeMaxDynamicSharedMemorySize, GEMM_SMEM);
    cudaFuncSetAttribute(gemm_hmma_f32,
                         cudaFuncAttributeMaxDynamicSharedMemorySize, GEMM_SMEM);
    cudaFuncSetAttribute(attn_hmma,
                         cudaFuncAttributeMaxDynamicSharedMemorySize, ATTN_SMEM);

    __nv_bfloat16 *qhi, *qlo, *khi, *klo, *vhi, *vlo, *chi, *clo;
    __nv_bfloat16 *xhi, *xlo, *wthi, *wtlo;
    cudaGetSymbolAddress((void**)&qhi, g_Qhi);
    cudaGetSymbolAddress((void**)&qlo, g_Qlo);
    cudaGetSymbolAddress((void**)&khi, g_Khi);
    cudaGetSymbolAddress((void**)&klo, g_Klo);
    cudaGetSymbolAddress((void**)&vhi, g_Vhi);
    cudaGetSymbolAddress((void**)&vlo, g_Vlo);
    cudaGetSymbolAddress((void**)&chi, g_chi);
    cudaGetSymbolAddress((void**)&clo, g_clo);
    cudaGetSymbolAddress((void**)&xhi, g_xhi);
    cudaGetSymbolAddress((void**)&xlo, g_xlo);
    cudaGetSymbolAddress((void**)&wthi, g_WThi);
    cudaGetSymbolAddress((void**)&wtlo, g_WTlo);

    const int nelem = MTOT * H;
    const size_t WSZ = (size_t)H * H;

    split_bf16_v4<<<(nelem / 4 + 255) / 256, 256>>>(x, xhi, xlo, nelem / 4);
    dim3 tgrid(H / 32, H / 32, 4), tblk(32, 8);
    transpose_split4<<<tgrid, tblk>>>(Wq, Wk, Wv, Wo, wthi, wtlo);

    dim3 ggrid(H / 128, MTOT / 128);   // (8, 32)
    gemm_hmma_split<<<ggrid, 256, GEMM_SMEM>>>(xhi, xlo,
        wthi + 0 * WSZ, wtlo + 0 * WSZ, bq, QSCALE, qhi, qlo);
    gemm_hmma_split<<<ggrid, 256, GEMM_SMEM>>>(xhi, xlo,
        wthi + 1 * WSZ, wtlo + 1 * WSZ, bk, 1.0f, khi, klo);
    gemm_hmma_split<<<ggrid, 256, GEMM_SMEM>>>(xhi, xlo,
        wthi + 2 * WSZ, wtlo + 2 * WSZ, bv, 1.0f, vhi, vlo);

    dim3 agrid(SEQ / 64, BSZ * NH);    // (32, 32)
    attn_hmma<<<agrid, 128, ATTN_SMEM>>>(qhi, qlo, khi, klo, vhi, vlo, chi, clo);

    gemm_hmma_f32<<<ggrid, 256, GEMM_SMEM>>>(chi, clo,
        wthi + 3 * WSZ, wtlo + 3 * WSZ, bo, out);
}

// round 7
// speedup vs baseline: 2.9617x; 1.0124x over previous
#include <cuda_runtime.h>
#include <cuda_bf16.h>
#include <math.h>
#include <stdint.h>

#define H   1024
#define NH  16
#define HD  64
#define BSZ 2
#define SEQ 2048
#define MTOT (BSZ*SEQ)   // 4096 rows

// 0.125 (1/sqrt(HD)) * log2(e): folded into Q projection
#define QSCALE 0.18033688011112042f

// ---------------------------------------------------------------------------
// Scratch (allocation-free rule: __device__ globals)
// ---------------------------------------------------------------------------
__device__ __nv_bfloat16 g_Qhi[MTOT * H];
__device__ __nv_bfloat16 g_Qlo[MTOT * H];
__device__ __nv_bfloat16 g_Khi[MTOT * H];
__device__ __nv_bfloat16 g_Klo[MTOT * H];
__device__ __nv_bfloat16 g_Vhi[MTOT * H];
__device__ __nv_bfloat16 g_Vlo[MTOT * H];
__device__ __nv_bfloat16 g_chi[MTOT * H];
__device__ __nv_bfloat16 g_clo[MTOT * H];
__device__ __nv_bfloat16 g_xhi[MTOT * H];
__device__ __nv_bfloat16 g_xlo[MTOT * H];
__device__ __nv_bfloat16 g_WThi[4][H * H];   // W^T (q,k,v,o contiguous), bf16-hi
__device__ __nv_bfloat16 g_WTlo[4][H * H];   // W^T, bf16-lo

// ---------------------------------------------------------------------------
// helpers
// ---------------------------------------------------------------------------
__device__ __forceinline__ uint32_t smem_u32(const void* p) {
    uint32_t a;
    asm("{ .reg .u64 t; cvta.to.shared.u64 t, %1; cvt.u32.u64 %0, t; }"
        : "=r"(a) : "l"(p));
    return a;
}
__device__ __forceinline__ void ldsm_x4(uint32_t* r, uint32_t addr) {
    asm volatile("ldmatrix.sync.aligned.m8n8.x4.shared.b16 {%0,%1,%2,%3}, [%4];"
                 : "=r"(r[0]), "=r"(r[1]), "=r"(r[2]), "=r"(r[3]) : "r"(addr));
}
__device__ __forceinline__ void ldsm_x2(uint32_t* r, uint32_t addr) {
    asm volatile("ldmatrix.sync.aligned.m8n8.x2.shared.b16 {%0,%1}, [%2];"
                 : "=r"(r[0]), "=r"(r[1]) : "r"(addr));
}
__device__ __forceinline__ void ldsm_x2t(uint32_t* r, uint32_t addr) {
    asm volatile("ldmatrix.sync.aligned.m8n8.x2.trans.shared.b16 {%0,%1}, [%2];"
                 : "=r"(r[0]), "=r"(r[1]) : "r"(addr));
}
__device__ __forceinline__ void mma_bf16(float* c, const uint32_t* a,
                                         const uint32_t* b) {
    asm volatile(
        "mma.sync.aligned.m16n8k16.row.col.f32.bf16.bf16.f32 "
        "{%0,%1,%2,%3}, {%4,%5,%6,%7}, {%8,%9}, {%0,%1,%2,%3};"
        : "+f"(c[0]), "+f"(c[1]), "+f"(c[2]), "+f"(c[3])
        : "r"(a[0]), "r"(a[1]), "r"(a[2]), "r"(a[3]), "r"(b[0]), "r"(b[1]));
}
__device__ __forceinline__ float exp2a(float x) {
    float y;
    asm("ex2.approx.f32 %0, %1;" : "=f"(y) : "f"(x));
    return y;
}
__device__ __forceinline__ void split2(float a, float b, uint32_t& hi, uint32_t& lo) {
    __nv_bfloat162 h = __floats2bfloat162_rn(a, b);
    float ra = a - __bfloat162float(h.x);
    float rb = b - __bfloat162float(h.y);
    __nv_bfloat162 l = __floats2bfloat162_rn(ra, rb);
    hi = *(uint32_t*)&h;
    lo = *(uint32_t*)&l;
}
__device__ __forceinline__ void cp16(uint32_t saddr, const void* g) {
    asm volatile("cp.async.cg.shared.global [%0], [%1], 16;"
                 :: "r"(saddr), "l"(g) : "memory");
}
__device__ __forceinline__ void cp_commit() {
    asm volatile("cp.async.commit_group;" ::: "memory");
}
template <int N>
__device__ __forceinline__ void cp_wait() {
    asm volatile("cp.async.wait_group %0;" :: "n"(N) : "memory");
}

// ---------------------------------------------------------------------------
// Prep
// ---------------------------------------------------------------------------
__global__ __launch_bounds__(256) void split_bf16_v4(
    const float* __restrict__ src, __nv_bfloat16* __restrict__ hi,
    __nv_bfloat16* __restrict__ lo, int n4)
{
    int i = blockIdx.x * 256 + threadIdx.x;
    if (i < n4) {
        float4 v = ((const float4*)src)[i];
        __nv_bfloat162 h0 = __floats2bfloat162_rn(v.x, v.y);
        __nv_bfloat162 h1 = __floats2bfloat162_rn(v.z, v.w);
        __nv_bfloat162 l0 = __floats2bfloat162_rn(v.x - __bfloat162float(h0.x),
                                                  v.y - __bfloat162float(h0.y));
        __nv_bfloat162 l1 = __floats2bfloat162_rn(v.z - __bfloat162float(h1.x),
                                                  v.w - __bfloat162float(h1.y));
        uint2 ho = { *(uint32_t*)&h0, *(uint32_t*)&h1 };
        uint2 loo = { *(uint32_t*)&l0, *(uint32_t*)&l1 };
        ((uint2*)hi)[i] = ho;
        ((uint2*)lo)[i] = loo;
    }
}

__global__ __launch_bounds__(256) void transpose_split4(
    const float* __restrict__ W0, const float* __restrict__ W1,
    const float* __restrict__ W2, const float* __restrict__ W3,
    __nv_bfloat16* __restrict__ hi, __nv_bfloat16* __restrict__ lo)
{
    __shared__ float t[32][33];
    const int z = blockIdx.z;
    const float* W = (z == 0) ? W0 : (z == 1) ? W1 : (z == 2) ? W2 : W3;
    const size_t off = (size_t)z * H * H;
    const int tx = threadIdx.x, ty = threadIdx.y;   // (32, 8)
    const int bx = blockIdx.x, by = blockIdx.y;
    #pragma unroll
    for (int i = 0; i < 4; i++)
        t[ty + 8 * i][tx] = W[(size_t)(by * 32 + ty + 8 * i) * H + bx * 32 + tx];
    __syncthreads();
    #pragma unroll
    for (int i = 0; i < 4; i++) {
        float v = t[tx][ty + 8 * i];
        int n = bx * 32 + ty + 8 * i;
        int k = by * 32 + tx;
        __nv_bfloat16 h = __float2bfloat16(v);
        hi[off + (size_t)n * H + k] = h;
        lo[off + (size_t)n * H + k] = __float2bfloat16(v - __bfloat162float(h));
    }
}

// ---------------------------------------------------------------------------
// HMMA split-bf16 GEMM mainloop (shared): 128x128 CTA tile, BK=32, 8 warps,
// 2-stage cp.async, one barrier per iter, mf-pipelined A fragments.
// Bhi/Blo passed pre-offset by n0*H.
// ---------------------------------------------------------------------------
#define ROWB 80
#define TILEB (128 * ROWB)            // 10240
#define STAGEB (4 * TILEB)            // 40960
#define GEMM_SMEM (2 * STAGEB)        // 81920

__device__ __forceinline__ void gemm_mainloop(
    const __nv_bfloat16* __restrict__ Ahi, const __nv_bfloat16* __restrict__ Alo,
    const __nv_bfloat16* __restrict__ Bhi, const __nv_bfloat16* __restrict__ Blo,
    int m0, uint32_t sb, float acc[4][4][4])
{
    const int tid  = threadIdx.x;
    const int wid  = tid >> 5;
    const int lane = tid & 31;
    const int warp_m = wid >> 2;
    const int warp_n = wid & 3;

    const uint32_t a_row = (lane & 15);
    const uint32_t a_koff = (lane >> 4) * 16;
    const uint32_t b_row = (lane & 7);
    const uint32_t b_koff = ((lane >> 3) & 1) * 16;

    const int g_row0 = tid >> 2;
    const int g_u4   = tid & 3;

    auto load_stage = [&](int stage, int k0) {
        const uint32_t st = sb + stage * STAGEB;
        #pragma unroll
        for (int i = 0; i < 2; i++) {
            const int row = g_row0 + i * 64;
            const uint32_t so = (uint32_t)row * ROWB + g_u4 * 16;
            const size_t ga = (size_t)(m0 + row) * H + k0 + g_u4 * 8;
            const size_t gb = (size_t)row * H + k0 + g_u4 * 8;
            cp16(st + 0 * TILEB + so, Ahi + ga);
            cp16(st + 1 * TILEB + so, Alo + ga);
            cp16(st + 2 * TILEB + so, Bhi + gb);
            cp16(st + 3 * TILEB + so, Blo + gb);
        }
        cp_commit();
    };

    load_stage(0, 0);

    for (int kc = 0; kc < 32; kc++) {
        cp_wait<0>();
        __syncthreads();
        if (kc < 31) load_stage((kc + 1) & 1, (kc + 1) * 32);

        const uint32_t st = sb + (kc & 1) * STAGEB;
        const uint32_t S_AHI = st, S_ALO = st + TILEB,
                       S_BHI = st + 2 * TILEB, S_BLO = st + 3 * TILEB;

        #pragma unroll
        for (int ks = 0; ks < 2; ks++) {
            const uint32_t kb = ks * 32;
            uint32_t bh[4][2], bl[4][2];
            #pragma unroll
            for (int nf = 0; nf < 4; nf++) {
                const uint32_t boff =
                    (uint32_t)(warp_n * 32 + nf * 8 + b_row) * ROWB + kb + b_koff;
                ldsm_x2(bh[nf], S_BHI + boff);
                ldsm_x2(bl[nf], S_BLO + boff);
            }
            // software-pipelined A fragments over mf
            uint32_t ah[2][4], al[2][4];
            {
                const uint32_t a0 =
                    (uint32_t)(warp_m * 64 + a_row) * ROWB + kb + a_koff;
                ldsm_x4(ah[0], S_AHI + a0);
                ldsm_x4(al[0], S_ALO + a0);
            }
            #pragma unroll
            for (int mf = 0; mf < 4; mf++) {
                const int cur = mf & 1;
                if (mf < 3) {
                    const uint32_t an =
                        (uint32_t)(warp_m * 64 + (mf + 1) * 16 + a_row) * ROWB
                        + kb + a_koff;
                    ldsm_x4(ah[cur ^ 1], S_AHI + an);
                    ldsm_x4(al[cur ^ 1], S_ALO + an);
                }
                #pragma unroll
                for (int nf = 0; nf < 4; nf++) {
                    mma_bf16(acc[mf][nf], ah[cur], bh[nf]);
                    mma_bf16(acc[mf][nf], ah[cur], bl[nf]);
                    mma_bf16(acc[mf][nf], al[cur], bh[nf]);
                }
            }
        }
    }
}

// Fused QKV projection: B = concatenated [3072 x 1024] W^T; epilogue selects
// section by n0 (0:Q scaled by QSCALE, 1:K, 2:V), writes split bf16.
__global__ __launch_bounds__(256, 2) void gemm_qkv(
    const __nv_bfloat16* __restrict__ Ahi, const __nv_bfloat16* __restrict__ Alo,
    const __nv_bfloat16* __restrict__ WThi, const __nv_bfloat16* __restrict__ WTlo,
    const float* __restrict__ bq, const float* __restrict__ bk,
    const float* __restrict__ bv,
    __nv_bfloat16* __restrict__ Qhi, __nv_bfloat16* __restrict__ Qlo,
    __nv_bfloat16* __restrict__ Khi, __nv_bfloat16* __restrict__ Klo,
    __nv_bfloat16* __restrict__ Vhi, __nv_bfloat16* __restrict__ Vlo)
{
    extern __shared__ __align__(16) char smem[];
    const uint32_t sb = smem_u32(smem);
    const int m0 = blockIdx.y * 128;
    const int n0 = blockIdx.x * 128;   // 0..2944

    float acc[4][4][4];
    #pragma unroll
    for (int i = 0; i < 4; i++)
        #pragma unroll
        for (int j = 0; j < 4; j++)
            #pragma unroll
            for (int r = 0; r < 4; r++) acc[i][j][r] = 0.0f;

    gemm_mainloop(Ahi, Alo, WThi + (size_t)n0 * H, WTlo + (size_t)n0 * H,
                  m0, sb, acc);

    const int sec = n0 >> 10;
    const float* bias = (sec == 0) ? bq : (sec == 1) ? bk : bv;
    const float scale = (sec == 0) ? QSCALE : 1.0f;
    __nv_bfloat16* Chi = (sec == 0) ? Qhi : (sec == 1) ? Khi : Vhi;
    __nv_bfloat16* Clo = (sec == 0) ? Qlo : (sec == 1) ? Klo : Vlo;
    const int nloc0 = n0 & 1023;

    const int tid  = threadIdx.x;
    const int wid  = tid >> 5;
    const int lane = tid & 31;
    const int warp_m = wid >> 2;
    const int warp_n = wid & 3;
    const int r_in = lane >> 2;
    const int c_in = (lane & 3) * 2;
    #pragma unroll
    for (int nf = 0; nf < 4; nf++) {
        const int col = nloc0 + warp_n * 32 + nf * 8 + c_in;
        const float2 bv2 = *(const float2*)(bias + col);
        #pragma unroll
        for (int mf = 0; mf < 4; mf++) {
            const int row = m0 + warp_m * 64 + mf * 16 + r_in;
            float v00 = (acc[mf][nf][0] + bv2.x) * scale;
            float v01 = (acc[mf][nf][1] + bv2.y) * scale;
            float v10 = (acc[mf][nf][2] + bv2.x) * scale;
            float v11 = (acc[mf][nf][3] + bv2.y) * scale;
            uint32_t h0, l0, h1, l1;
            split2(v00, v01, h0, l0);
            split2(v10, v11, h1, l1);
            *(uint32_t*)(Chi + (size_t)row * H + col) = h0;
            *(uint32_t*)(Clo + (size_t)row * H + col) = l0;
            *(uint32_t*)(Chi + (size_t)(row + 8) * H + col) = h1;
            *(uint32_t*)(Clo + (size_t)(row + 8) * H + col) = l1;
        }
    }
}

// Output projection: f32 out
__global__ __launch_bounds__(256, 2) void gemm_o(
    const __nv_bfloat16* __restrict__ Ahi, const __nv_bfloat16* __restrict__ Alo,
    const __nv_bfloat16* __restrict__ WThi, const __nv_bfloat16* __restrict__ WTlo,
    const float* __restrict__ bias, float* __restrict__ C)
{
    extern __shared__ __align__(16) char smem[];
    const uint32_t sb = smem_u32(smem);
    const int m0 = blockIdx.y * 128;
    const int n0 = blockIdx.x * 128;

    float acc[4][4][4];
    #pragma unroll
    for (int i = 0; i < 4; i++)
        #pragma unroll
        for (int j = 0; j < 4; j++)
            #pragma unroll
            for (int r = 0; r < 4; r++) acc[i][j][r] = 0.0f;

    gemm_mainloop(Ahi, Alo, WThi + (size_t)n0 * H, WTlo + (size_t)n0 * H,
                  m0, sb, acc);

    const int tid  = threadIdx.x;
    const int wid  = tid >> 5;
    const int lane = tid & 31;
    const int warp_m = wid >> 2;
    const int warp_n = wid & 3;
    const int r_in = lane >> 2;
    const int c_in = (lane & 3) * 2;
    #pragma unroll
    for (int nf = 0; nf < 4; nf++) {
        const int col = n0 + warp_n * 32 + nf * 8 + c_in;
        const float2 bv2 = *(const float2*)(bias + col);
        #pragma unroll
        for (int mf = 0; mf < 4; mf++) {
            const int row = m0 + warp_m * 64 + mf * 16 + r_in;
            float2 o0 = { acc[mf][nf][0] + bv2.x, acc[mf][nf][1] + bv2.y };
            float2 o1 = { acc[mf][nf][2] + bv2.x, acc[mf][nf][3] + bv2.y };
            *(float2*)(C + (size_t)row * H + col) = o0;
            *(float2*)(C + (size_t)(row + 8) * H + col) = o1;
        }
    }
}

// ---------------------------------------------------------------------------
// HMMA flash attention, Bc=64 KV tiles, 2-stage cp.async, one barrier/iter.
// grid (SEQ/64, BSZ*NH), 128 threads (4 warps). Warp w owns q rows w*16..+15.
// ---------------------------------------------------------------------------
#define AROW 144
#define QTILE (64 * AROW)              // 9216
#define KVTILE (64 * AROW)             // 9216
#define KVSTAGE (4 * KVTILE)           // 36864
#define ATTN_SMEM (2 * QTILE + 2 * KVSTAGE)   // 92160

__global__ __launch_bounds__(128) void attn_hmma(
    const __nv_bfloat16* __restrict__ Qhi, const __nv_bfloat16* __restrict__ Qlo,
    const __nv_bfloat16* __restrict__ Khi, const __nv_bfloat16* __restrict__ Klo,
    const __nv_bfloat16* __restrict__ Vhi, const __nv_bfloat16* __restrict__ Vlo,
    __nv_bfloat16* __restrict__ Chi, __nv_bfloat16* __restrict__ Clo)
{
    extern __shared__ __align__(16) char smem[];
    const uint32_t sb = smem_u32(smem);
    const uint32_t S_QH = 0, S_QL = QTILE;

    const int tid  = threadIdx.x;
    const int warp = tid >> 5;
    const int lane = tid & 31;
    const int qb = blockIdx.x;
    const int b  = blockIdx.y / NH;
    const int h  = blockIdx.y % NH;
    const size_t hcol = (size_t)h * HD;
    const size_t rbase = (size_t)b * SEQ;

    #pragma unroll
    for (int t = 0; t < 4; t++) {
        const int idx = tid + t * 128;
        const int r = idx >> 3, c = idx & 7;
        const uint32_t so = (uint32_t)r * AROW + c * 16;
        const size_t g = (rbase + qb * 64 + r) * H + hcol + c * 8;
        cp16(sb + S_QH + so, Qhi + g);
        cp16(sb + S_QL + so, Qlo + g);
    }
    cp_commit();

    auto load_kv = [&](int stage, int kb) {
        const uint32_t st = sb + 2 * QTILE + stage * KVSTAGE;
        #pragma unroll
        for (int t = 0; t < 4; t++) {
            const int idx = tid + t * 128;
            const int r = idx >> 3, c = idx & 7;
            const uint32_t so = (uint32_t)r * AROW + c * 16;
            const size_t g = (rbase + kb * 64 + r) * H + hcol + c * 8;
            cp16(st + 0 * KVTILE + so, Khi + g);
            cp16(st + 1 * KVTILE + so, Klo + g);
            cp16(st + 2 * KVTILE + so, Vhi + g);
            cp16(st + 3 * KVTILE + so, Vlo + g);
        }
        cp_commit();
    };

    float O[8][4];
    #pragma unroll
    for (int d = 0; d < 8; d++)
        #pragma unroll
        for (int r = 0; r < 4; r++) O[d][r] = 0.0f;
    float m0 = -1e30f, m1 = -1e30f, l0 = 0.0f, l1 = 0.0f;

    const uint32_t a_base = S_QH + (uint32_t)(warp * 16 + (lane & 15)) * AROW
                          + (lane >> 4) * 16;
    const uint32_t al_base = a_base + QTILE;
    const uint32_t b_rowoff = (uint32_t)(lane & 7) * AROW + ((lane >> 3) & 1) * 16;
    const uint32_t v_laneoff = (uint32_t)(lane & 15) * AROW;

    const int r_in = lane >> 2;
    const int c_in = (lane & 3) * 2;

    const int nkb = qb + 1;
    load_kv(0, 0);

    for (int kb = 0; kb < nkb; kb++) {
        cp_wait<0>();
        __syncthreads();
        if (kb + 1 < nkb) load_kv((kb + 1) & 1, kb + 1);

        const uint32_t st = sb + 2 * QTILE + (kb & 1) * KVSTAGE;
        const uint32_t S_KH = st, S_KL = st + KVTILE,
                       S_VH = st + 2 * KVTILE, S_VL = st + 3 * KVTILE;

        float s[8][4];
        #pragma unroll
        for (int nf = 0; nf < 8; nf++)
            #pragma unroll
            for (int r = 0; r < 4; r++) s[nf][r] = 0.0f;

        #pragma unroll
        for (int ks = 0; ks < 4; ks++) {
            uint32_t ah[4], al[4];
            ldsm_x4(ah, sb + a_base + ks * 32);
            ldsm_x4(al, sb + al_base + ks * 32);
            #pragma unroll
            for (int nf = 0; nf < 8; nf++) {
                uint32_t bh[2], bl[2];
                const uint32_t bo = (uint32_t)(nf * 8) * AROW + b_rowoff + ks * 32;
                ldsm_x2(bh, S_KH + bo);
                ldsm_x2(bl, S_KL + bo);
                mma_bf16(s[nf], ah, bh);
                mma_bf16(s[nf], ah, bl);
                mma_bf16(s[nf], al, bh);
            }
        }

        if (kb == qb) {
            const int row0 = qb * 64 + warp * 16 + r_in;
            const int row1 = row0 + 8;
            #pragma unroll
            for (int nf = 0; nf < 8; nf++) {
                const int cg = kb * 64 + nf * 8 + c_in;
                if (cg > row0)     s[nf][0] = -1e30f;
                if (cg + 1 > row0) s[nf][1] = -1e30f;
                if (cg > row1)     s[nf][2] = -1e30f;
                if (cg + 1 > row1) s[nf][3] = -1e30f;
            }
        }

        float rmax0 = -1e30f, rmax1 = -1e30f;
        #pragma unroll
        for (int nf = 0; nf < 8; nf++) {
            rmax0 = fmaxf(rmax0, fmaxf(s[nf][0], s[nf][1]));
            rmax1 = fmaxf(rmax1, fmaxf(s[nf][2], s[nf][3]));
        }
        rmax0 = fmaxf(rmax0, __shfl_xor_sync(0xffffffffu, rmax0, 1));
        rmax0 = fmaxf(rmax0, __shfl_xor_sync(0xffffffffu, rmax0, 2));
        rmax1 = fmaxf(rmax1, __shfl_xor_sync(0xffffffffu, rmax1, 1));
        rmax1 = fmaxf(rmax1, __shfl_xor_sync(0xffffffffu, rmax1, 2));
        const float mn0 = fmaxf(m0, rmax0);
        const float mn1 = fmaxf(m1, rmax1);
        const float sc0 = exp2a(m0 - mn0);
        const float sc1 = exp2a(m1 - mn1);

        float rs0 = 0.0f, rs1 = 0.0f;
        uint32_t phi01[8], phi23[8], plo01[8], plo23[8];
        #pragma unroll
        for (int nf = 0; nf < 8; nf++) {
            float p00 = exp2a(s[nf][0] - mn0);
            float p01 = exp2a(s[nf][1] - mn0);
            float p10 = exp2a(s[nf][2] - mn1);
            float p11 = exp2a(s[nf][3] - mn1);
            rs0 += p00 + p01;
            rs1 += p10 + p11;
            split2(p00, p01, phi01[nf], plo01[nf]);
            split2(p10, p11, phi23[nf], plo23[nf]);
        }
        rs0 += __shfl_xor_sync(0xffffffffu, rs0, 1);
        rs0 += __shfl_xor_sync(0xffffffffu, rs0, 2);
        rs1 += __shfl_xor_sync(0xffffffffu, rs1, 1);
        rs1 += __shfl_xor_sync(0xffffffffu, rs1, 2);
        l0 = l0 * sc0 + rs0;
        l1 = l1 * sc1 + rs1;
        m0 = mn0; m1 = mn1;
        #pragma unroll
        for (int d = 0; d < 8; d++) {
            O[d][0] *= sc0; O[d][1] *= sc0;
            O[d][2] *= sc1; O[d][3] *= sc1;
        }

        #pragma unroll
        for (int ksj = 0; ksj < 4; ksj++) {
            const uint32_t ph[4] = { phi01[2*ksj], phi23[2*ksj],
                                     phi01[2*ksj+1], phi23[2*ksj+1] };
            const uint32_t pl[4] = { plo01[2*ksj], plo23[2*ksj],
                                     plo01[2*ksj+1], plo23[2*ksj+1] };
            const uint32_t vbase = (uint32_t)(ksj * 16) * AROW + v_laneoff;
            #pragma unroll
            for (int df = 0; df < 8; df++) {
                uint32_t vh[2], vl[2];
                ldsm_x2t(vh, S_VH + vbase + df * 16);
                ldsm_x2t(vl, S_VL + vbase + df * 16);
                mma_bf16(O[df], ph, vh);
                mma_bf16(O[df], ph, vl);
                mma_bf16(O[df], pl, vh);
            }
        }
    }

    const float inv0 = 1.0f / l0;
    const float inv1 = 1.0f / l1;
    const int row0 = qb * 64 + warp * 16 + r_in;
    #pragma unroll
    for (int df = 0; df < 8; df++) {
        const size_t col = hcol + df * 8 + c_in;
        uint32_t h0, lo0, h1, lo1;
        split2(O[df][0] * inv0, O[df][1] * inv0, h0, lo0);
        split2(O[df][2] * inv1, O[df][3] * inv1, h1, lo1);
        *(uint32_t*)(Chi + (rbase + row0) * H + col) = h0;
        *(uint32_t*)(Clo + (rbase + row0) * H + col) = lo0;
        *(uint32_t*)(Chi + (rbase + row0 + 8) * H + col) = h1;
        *(uint32_t*)(Clo + (rbase + row0 + 8) * H + col) = lo1;
    }
}

// ---------------------------------------------------------------------------
extern "C" void kernel_launch(void* const* d_in, const int* in_sizes, int n_in,
                              void* d_out, int out_size)
{
    const float* x  = (const float*)d_in[0];
    const float* Wq = (const float*)d_in[1];
    const float* bq = (const float*)d_in[2];
    const float* Wk = (const float*)d_in[3];
    const float* bk = (const float*)d_in[4];
    const float* Wv = (const float*)d_in[5];
    const float* bv = (const float*)d_in[6];
    const float* Wo = (const float*)d_in[7];
    const float* bo = (const float*)d_in[8];
    float* out = (float*)d_out;

    cudaFuncSetAttribute(gemm_qkv,
                         cudaFuncAttributeMaxDynamicSharedMemorySize, GEMM_SMEM);
    cudaFuncSetAttribute(gemm_o,
                         cudaFuncAttributeMaxDynamicSharedMemorySize, GEMM_SMEM);
    cudaFuncSetAttribute(attn_hmma,
                         cudaFuncAttributeMaxDynamicSharedMemorySize, ATTN_SMEM);

    __nv_bfloat16 *qhi, *qlo, *khi, *klo, *vhi, *vlo, *chi, *clo;
    __nv_bfloat16 *xhi, *xlo, *wthi, *wtlo;
    cudaGetSymbolAddress((void**)&qhi, g_Qhi);
    cudaGetSymbolAddress((void**)&qlo, g_Qlo);
    cudaGetSymbolAddress((void**)&khi, g_Khi);
    cudaGetSymbolAddress((void**)&klo, g_Klo);
    cudaGetSymbolAddress((void**)&vhi, g_Vhi);
    cudaGetSymbolAddress((void**)&vlo, g_Vlo);
    cudaGetSymbolAddress((void**)&chi, g_chi);
    cudaGetSymbolAddress((void**)&clo, g_clo);
    cudaGetSymbolAddress((void**)&xhi, g_xhi);
    cudaGetSymbolAddress((void**)&xlo, g_xlo);
    cudaGetSymbolAddress((void**)&wthi, g_WThi);
    cudaGetSymbolAddress((void**)&wtlo, g_WTlo);

    const int nelem = MTOT * H;
    const size_t WSZ = (size_t)H * H;

    split_bf16_v4<<<(nelem / 4 + 255) / 256, 256>>>(x, xhi, xlo, nelem / 4);
    dim3 tgrid(H / 32, H / 32, 4), tblk(32, 8);
    transpose_split4<<<tgrid, tblk>>>(Wq, Wk, Wv, Wo, wthi, wtlo);

    // fused QKV projection: N = 3072
    dim3 qkvgrid(3 * H / 128, MTOT / 128);   // (24, 32)
    gemm_qkv<<<qkvgrid, 256, GEMM_SMEM>>>(xhi, xlo, wthi, wtlo,
        bq, bk, bv, qhi, qlo, khi, klo, vhi, vlo);

    dim3 agrid(SEQ / 64, BSZ * NH);          // (32, 32)
    attn_hmma<<<agrid, 128, ATTN_SMEM>>>(qhi, qlo, khi, klo, vhi, vlo, chi, clo);

    dim3 ogrid(H / 128, MTOT / 128);         // (8, 32)
    gemm_o<<<ogrid, 256, GEMM_SMEM>>>(chi, clo, wthi + 3 * WSZ, wtlo + 3 * WSZ,
                                      bo, out);
}

// round 8
// speedup vs baseline: 3.0000x; 1.0129x over previous
#include <cuda_runtime.h>
#include <cuda_bf16.h>
#include <math.h>
#include <stdint.h>

#define H   1024
#define NH  16
#define HD  64
#define BSZ 2
#define SEQ 2048
#define MTOT (BSZ*SEQ)   // 4096 rows

// 0.125 (1/sqrt(HD)) * log2(e): folded into Q projection
#define QSCALE 0.18033688011112042f

// ---------------------------------------------------------------------------
// Scratch (allocation-free rule: __device__ globals)
// ---------------------------------------------------------------------------
__device__ __nv_bfloat16 g_Qhi[MTOT * H];
__device__ __nv_bfloat16 g_Qlo[MTOT * H];
__device__ __nv_bfloat16 g_Khi[MTOT * H];
__device__ __nv_bfloat16 g_Klo[MTOT * H];
__device__ __nv_bfloat16 g_Vhi[MTOT * H];
__device__ __nv_bfloat16 g_Vlo[MTOT * H];
__device__ __nv_bfloat16 g_chi[MTOT * H];
__device__ __nv_bfloat16 g_clo[MTOT * H];
__device__ __nv_bfloat16 g_xhi[MTOT * H];
__device__ __nv_bfloat16 g_xlo[MTOT * H];
__device__ __nv_bfloat16 g_WThi[4][H * H];   // W^T (q,k,v,o contiguous), bf16-hi
__device__ __nv_bfloat16 g_WTlo[4][H * H];   // W^T, bf16-lo

// ---------------------------------------------------------------------------
// helpers
// ---------------------------------------------------------------------------
__device__ __forceinline__ uint32_t smem_u32(const void* p) {
    uint32_t a;
    asm("{ .reg .u64 t; cvta.to.shared.u64 t, %1; cvt.u32.u64 %0, t; }"
        : "=r"(a) : "l"(p));
    return a;
}
__device__ __forceinline__ void ldsm_x4(uint32_t* r, uint32_t addr) {
    asm volatile("ldmatrix.sync.aligned.m8n8.x4.shared.b16 {%0,%1,%2,%3}, [%4];"
                 : "=r"(r[0]), "=r"(r[1]), "=r"(r[2]), "=r"(r[3]) : "r"(addr));
}
__device__ __forceinline__ void ldsm_x4t(uint32_t* r, uint32_t addr) {
    asm volatile("ldmatrix.sync.aligned.m8n8.x4.trans.shared.b16 {%0,%1,%2,%3}, [%4];"
                 : "=r"(r[0]), "=r"(r[1]), "=r"(r[2]), "=r"(r[3]) : "r"(addr));
}
__device__ __forceinline__ void mma_bf16(float* c, const uint32_t* a,
                                         const uint32_t* b) {
    asm volatile(
        "mma.sync.aligned.m16n8k16.row.col.f32.bf16.bf16.f32 "
        "{%0,%1,%2,%3}, {%4,%5,%6,%7}, {%8,%9}, {%0,%1,%2,%3};"
        : "+f"(c[0]), "+f"(c[1]), "+f"(c[2]), "+f"(c[3])
        : "r"(a[0]), "r"(a[1]), "r"(a[2]), "r"(a[3]), "r"(b[0]), "r"(b[1]));
}
__device__ __forceinline__ float exp2a(float x) {
    float y;
    asm("ex2.approx.f32 %0, %1;" : "=f"(y) : "f"(x));
    return y;
}
__device__ __forceinline__ void split2(float a, float b, uint32_t& hi, uint32_t& lo) {
    __nv_bfloat162 h = __floats2bfloat162_rn(a, b);
    float ra = a - __bfloat162float(h.x);
    float rb = b - __bfloat162float(h.y);
    __nv_bfloat162 l = __floats2bfloat162_rn(ra, rb);
    hi = *(uint32_t*)&h;
    lo = *(uint32_t*)&l;
}
__device__ __forceinline__ void cp16(uint32_t saddr, const void* g) {
    asm volatile("cp.async.cg.shared.global [%0], [%1], 16;"
                 :: "r"(saddr), "l"(g) : "memory");
}
__device__ __forceinline__ void cp_commit() {
    asm volatile("cp.async.commit_group;" ::: "memory");
}
template <int N>
__device__ __forceinline__ void cp_wait() {
    asm volatile("cp.async.wait_group %0;" :: "n"(N) : "memory");
}

// ---------------------------------------------------------------------------
// Prep
// ---------------------------------------------------------------------------
__global__ __launch_bounds__(256) void split_bf16_v4(
    const float* __restrict__ src, __nv_bfloat16* __restrict__ hi,
    __nv_bfloat16* __restrict__ lo, int n4)
{
    int i = blockIdx.x * 256 + threadIdx.x;
    if (i < n4) {
        float4 v = ((const float4*)src)[i];
        __nv_bfloat162 h0 = __floats2bfloat162_rn(v.x, v.y);
        __nv_bfloat162 h1 = __floats2bfloat162_rn(v.z, v.w);
        __nv_bfloat162 l0 = __floats2bfloat162_rn(v.x - __bfloat162float(h0.x),
                                                  v.y - __bfloat162float(h0.y));
        __nv_bfloat162 l1 = __floats2bfloat162_rn(v.z - __bfloat162float(h1.x),
                                                  v.w - __bfloat162float(h1.y));
        uint2 ho = { *(uint32_t*)&h0, *(uint32_t*)&h1 };
        uint2 loo = { *(uint32_t*)&l0, *(uint32_t*)&l1 };
        ((uint2*)hi)[i] = ho;
        ((uint2*)lo)[i] = loo;
    }
}

__global__ __launch_bounds__(256) void transpose_split4(
    const float* __restrict__ W0, const float* __restrict__ W1,
    const float* __restrict__ W2, const float* __restrict__ W3,
    __nv_bfloat16* __restrict__ hi, __nv_bfloat16* __restrict__ lo)
{
    __shared__ float t[32][33];
    const int z = blockIdx.z;
    const float* W = (z == 0) ? W0 : (z == 1) ? W1 : (z == 2) ? W2 : W3;
    const size_t off = (size_t)z * H * H;
    const int tx = threadIdx.x, ty = threadIdx.y;   // (32, 8)
    const int bx = blockIdx.x, by = blockIdx.y;
    #pragma unroll
    for (int i = 0; i < 4; i++)
        t[ty + 8 * i][tx] = W[(size_t)(by * 32 + ty + 8 * i) * H + bx * 32 + tx];
    __syncthreads();
    #pragma unroll
    for (int i = 0; i < 4; i++) {
        float v = t[tx][ty + 8 * i];
        int n = bx * 32 + ty + 8 * i;
        int k = by * 32 + tx;
        __nv_bfloat16 h = __float2bfloat16(v);
        hi[off + (size_t)n * H + k] = h;
        lo[off + (size_t)n * H + k] = __float2bfloat16(v - __bfloat162float(h));
    }
}

// ---------------------------------------------------------------------------
// HMMA split-bf16 GEMM mainloop: 128x128 CTA tile, BK=32, 8 warps (2x4),
// 2-stage cp.async, one barrier per iter, x4 B loads, product-outer MMAs.
// ---------------------------------------------------------------------------
#define ROWB 80
#define TILEB (128 * ROWB)            // 10240
#define STAGEB (4 * TILEB)            // 40960
#define GEMM_SMEM (2 * STAGEB)        // 81920

__device__ __forceinline__ void gemm_mainloop(
    const __nv_bfloat16* __restrict__ Ahi, const __nv_bfloat16* __restrict__ Alo,
    const __nv_bfloat16* __restrict__ Bhi, const __nv_bfloat16* __restrict__ Blo,
    int m0, uint32_t sb, float acc[4][4][4])
{
    const int tid  = threadIdx.x;
    const int wid  = tid >> 5;
    const int lane = tid & 31;
    const int warp_m = wid >> 2;
    const int warp_n = wid & 3;

    const uint32_t a_row = (lane & 15);
    const uint32_t a_koff = (lane >> 4) * 16;
    // x4 paired-nf B load: rows (lane&7) + ((lane>>4)&1)*8, k-half (lane>>3)&1
    const uint32_t b_row16 = (lane & 7) + ((lane >> 4) & 1) * 8;
    const uint32_t b_koff = ((lane >> 3) & 1) * 16;

    const int g_row0 = tid >> 2;
    const int g_u4   = tid & 3;

    auto load_stage = [&](int stage, int k0) {
        const uint32_t st = sb + stage * STAGEB;
        #pragma unroll
        for (int i = 0; i < 2; i++) {
            const int row = g_row0 + i * 64;
            const uint32_t so = (uint32_t)row * ROWB + g_u4 * 16;
            const size_t ga = (size_t)(m0 + row) * H + k0 + g_u4 * 8;
            const size_t gb = (size_t)row * H + k0 + g_u4 * 8;
            cp16(st + 0 * TILEB + so, Ahi + ga);
            cp16(st + 1 * TILEB + so, Alo + ga);
            cp16(st + 2 * TILEB + so, Bhi + gb);
            cp16(st + 3 * TILEB + so, Blo + gb);
        }
        cp_commit();
    };

    load_stage(0, 0);

    for (int kc = 0; kc < 32; kc++) {
        cp_wait<0>();
        __syncthreads();
        if (kc < 31) load_stage((kc + 1) & 1, (kc + 1) * 32);

        const uint32_t st = sb + (kc & 1) * STAGEB;
        const uint32_t S_AHI = st, S_ALO = st + TILEB,
                       S_BHI = st + 2 * TILEB, S_BLO = st + 3 * TILEB;

        #pragma unroll
        for (int ks = 0; ks < 2; ks++) {
            const uint32_t kb = ks * 32;
            uint32_t bh[4][2], bl[4][2];
            #pragma unroll
            for (int nfp = 0; nfp < 2; nfp++) {
                const uint32_t boff =
                    (uint32_t)(warp_n * 32 + nfp * 16 + b_row16) * ROWB + kb + b_koff;
                ldsm_x4(&bh[2 * nfp][0], S_BHI + boff);
                ldsm_x4(&bl[2 * nfp][0], S_BLO + boff);
            }
            #pragma unroll
            for (int mf = 0; mf < 4; mf++) {
                const uint32_t aoff =
                    (uint32_t)(warp_m * 64 + mf * 16 + a_row) * ROWB + kb + a_koff;
                uint32_t ah[4], al[4];
                ldsm_x4(ah, S_AHI + aoff);
                ldsm_x4(al, S_ALO + aoff);
                // product-outer: reuse distance 4 on each acc
                #pragma unroll
                for (int nf = 0; nf < 4; nf++) mma_bf16(acc[mf][nf], ah, bh[nf]);
                #pragma unroll
                for (int nf = 0; nf < 4; nf++) mma_bf16(acc[mf][nf], ah, bl[nf]);
                #pragma unroll
                for (int nf = 0; nf < 4; nf++) mma_bf16(acc[mf][nf], al, bh[nf]);
            }
        }
    }
}

// Fused QKV projection: B = concatenated [3072 x 1024] W^T.
__global__ __launch_bounds__(256, 2) void gemm_qkv(
    const __nv_bfloat16* __restrict__ Ahi, const __nv_bfloat16* __restrict__ Alo,
    const __nv_bfloat16* __restrict__ WThi, const __nv_bfloat16* __restrict__ WTlo,
    const float* __restrict__ bq, const float* __restrict__ bk,
    const float* __restrict__ bv,
    __nv_bfloat16* __restrict__ Qhi, __nv_bfloat16* __restrict__ Qlo,
    __nv_bfloat16* __restrict__ Khi, __nv_bfloat16* __restrict__ Klo,
    __nv_bfloat16* __restrict__ Vhi, __nv_bfloat16* __restrict__ Vlo)
{
    extern __shared__ __align__(16) char smem[];
    const uint32_t sb = smem_u32(smem);
    const int m0 = blockIdx.y * 128;
    const int n0 = blockIdx.x * 128;   // 0..2944

    float acc[4][4][4];
    #pragma unroll
    for (int i = 0; i < 4; i++)
        #pragma unroll
        for (int j = 0; j < 4; j++)
            #pragma unroll
            for (int r = 0; r < 4; r++) acc[i][j][r] = 0.0f;

    gemm_mainloop(Ahi, Alo, WThi + (size_t)n0 * H, WTlo + (size_t)n0 * H,
                  m0, sb, acc);

    const int sec = n0 >> 10;
    const float* bias = (sec == 0) ? bq : (sec == 1) ? bk : bv;
    const float scale = (sec == 0) ? QSCALE : 1.0f;
    __nv_bfloat16* Chi = (sec == 0) ? Qhi : (sec == 1) ? Khi : Vhi;
    __nv_bfloat16* Clo = (sec == 0) ? Qlo : (sec == 1) ? Klo : Vlo;
    const int nloc0 = n0 & 1023;

    const int tid  = threadIdx.x;
    const int wid  = tid >> 5;
    const int lane = tid & 31;
    const int warp_m = wid >> 2;
    const int warp_n = wid & 3;
    const int r_in = lane >> 2;
    const int c_in = (lane & 3) * 2;
    #pragma unroll
    for (int nf = 0; nf < 4; nf++) {
        const int col = nloc0 + warp_n * 32 + nf * 8 + c_in;
        const float2 bv2 = *(const float2*)(bias + col);
        #pragma unroll
        for (int mf = 0; mf < 4; mf++) {
            const int row = m0 + warp_m * 64 + mf * 16 + r_in;
            float v00 = (acc[mf][nf][0] + bv2.x) * scale;
            float v01 = (acc[mf][nf][1] + bv2.y) * scale;
            float v10 = (acc[mf][nf][2] + bv2.x) * scale;
            float v11 = (acc[mf][nf][3] + bv2.y) * scale;
            uint32_t h0, l0, h1, l1;
            split2(v00, v01, h0, l0);
            split2(v10, v11, h1, l1);
            *(uint32_t*)(Chi + (size_t)row * H + col) = h0;
            *(uint32_t*)(Clo + (size_t)row * H + col) = l0;
            *(uint32_t*)(Chi + (size_t)(row + 8) * H + col) = h1;
            *(uint32_t*)(Clo + (size_t)(row + 8) * H + col) = l1;
        }
    }
}

// Output projection: f32 out
__global__ __launch_bounds__(256, 2) void gemm_o(
    const __nv_bfloat16* __restrict__ Ahi, const __nv_bfloat16* __restrict__ Alo,
    const __nv_bfloat16* __restrict__ WThi, const __nv_bfloat16* __restrict__ WTlo,
    const float* __restrict__ bias, float* __restrict__ C)
{
    extern __shared__ __align__(16) char smem[];
    const uint32_t sb = smem_u32(smem);
    const int m0 = blockIdx.y * 128;
    const int n0 = blockIdx.x * 128;

    float acc[4][4][4];
    #pragma unroll
    for (int i = 0; i < 4; i++)
        #pragma unroll
        for (int j = 0; j < 4; j++)
            #pragma unroll
            for (int r = 0; r < 4; r++) acc[i][j][r] = 0.0f;

    gemm_mainloop(Ahi, Alo, WThi + (size_t)n0 * H, WTlo + (size_t)n0 * H,
                  m0, sb, acc);

    const int tid  = threadIdx.x;
    const int wid  = tid >> 5;
    const int lane = tid & 31;
    const int warp_m = wid >> 2;
    const int warp_n = wid & 3;
    const int r_in = lane >> 2;
    const int c_in = (lane & 3) * 2;
    #pragma unroll
    for (int nf = 0; nf < 4; nf++) {
        const int col = n0 + warp_n * 32 + nf * 8 + c_in;
        const float2 bv2 = *(const float2*)(bias + col);
        #pragma unroll
        for (int mf = 0; mf < 4; mf++) {
            const int row = m0 + warp_m * 64 + mf * 16 + r_in;
            float2 o0 = { acc[mf][nf][0] + bv2.x, acc[mf][nf][1] + bv2.y };
            float2 o1 = { acc[mf][nf][2] + bv2.x, acc[mf][nf][3] + bv2.y };
            *(float2*)(C + (size_t)row * H + col) = o0;
            *(float2*)(C + (size_t)(row + 8) * H + col) = o1;
        }
    }
}

// ---------------------------------------------------------------------------
// HMMA flash attention, Bc=64 KV tiles, 2-stage cp.async, one barrier/iter.
// x4 K loads (paired nf), x4.trans V loads (paired ksj), P split on the fly.
// grid (SEQ/64, BSZ*NH), 128 threads (4 warps). Warp w owns q rows w*16..+15.
// ---------------------------------------------------------------------------
#define AROW 144
#define QTILE (64 * AROW)              // 9216
#define KVTILE (64 * AROW)             // 9216
#define KVSTAGE (4 * KVTILE)           // 36864
#define ATTN_SMEM (2 * QTILE + 2 * KVSTAGE)   // 92160

__global__ __launch_bounds__(128) void attn_hmma(
    const __nv_bfloat16* __restrict__ Qhi, const __nv_bfloat16* __restrict__ Qlo,
    const __nv_bfloat16* __restrict__ Khi, const __nv_bfloat16* __restrict__ Klo,
    const __nv_bfloat16* __restrict__ Vhi, const __nv_bfloat16* __restrict__ Vlo,
    __nv_bfloat16* __restrict__ Chi, __nv_bfloat16* __restrict__ Clo)
{
    extern __shared__ __align__(16) char smem[];
    const uint32_t sb = smem_u32(smem);
    const uint32_t S_QH = 0, S_QL = QTILE;

    const int tid  = threadIdx.x;
    const int warp = tid >> 5;
    const int lane = tid & 31;
    const int qb = blockIdx.x;
    const int b  = blockIdx.y / NH;
    const int h  = blockIdx.y % NH;
    const size_t hcol = (size_t)h * HD;
    const size_t rbase = (size_t)b * SEQ;

    #pragma unroll
    for (int t = 0; t < 4; t++) {
        const int idx = tid + t * 128;
        const int r = idx >> 3, c = idx & 7;
        const uint32_t so = (uint32_t)r * AROW + c * 16;
        const size_t g = (rbase + qb * 64 + r) * H + hcol + c * 8;
        cp16(sb + S_QH + so, Qhi + g);
        cp16(sb + S_QL + so, Qlo + g);
    }
    cp_commit();

    auto load_kv = [&](int stage, int kb) {
        const uint32_t st = sb + 2 * QTILE + stage * KVSTAGE;
        #pragma unroll
        for (int t = 0; t < 4; t++) {
            const int idx = tid + t * 128;
            const int r = idx >> 3, c = idx & 7;
            const uint32_t so = (uint32_t)r * AROW + c * 16;
            const size_t g = (rbase + kb * 64 + r) * H + hcol + c * 8;
            cp16(st + 0 * KVTILE + so, Khi + g);
            cp16(st + 1 * KVTILE + so, Klo + g);
            cp16(st + 2 * KVTILE + so, Vhi + g);
            cp16(st + 3 * KVTILE + so, Vlo + g);
        }
        cp_commit();
    };

    float O[8][4];
    #pragma unroll
    for (int d = 0; d < 8; d++)
        #pragma unroll
        for (int r = 0; r < 4; r++) O[d][r] = 0.0f;
    float m0 = -1e30f, m1 = -1e30f, l0 = 0.0f, l1 = 0.0f;

    const uint32_t a_base = S_QH + (uint32_t)(warp * 16 + (lane & 15)) * AROW
                          + (lane >> 4) * 16;
    const uint32_t al_base = a_base + QTILE;
    const uint32_t b_row16 = (lane & 7) + ((lane >> 4) & 1) * 8;
    const uint32_t b_koff = ((lane >> 3) & 1) * 16;

    const int r_in = lane >> 2;
    const int c_in = (lane & 3) * 2;

    const int nkb = qb + 1;
    load_kv(0, 0);

    for (int kb = 0; kb < nkb; kb++) {
        cp_wait<0>();
        __syncthreads();
        if (kb + 1 < nkb) load_kv((kb + 1) & 1, kb + 1);

        const uint32_t st = sb + 2 * QTILE + (kb & 1) * KVSTAGE;
        const uint32_t S_KH = st, S_KL = st + KVTILE,
                       S_VH = st + 2 * KVTILE, S_VL = st + 3 * KVTILE;

        float s[8][4];
        #pragma unroll
        for (int nf = 0; nf < 8; nf++)
            #pragma unroll
            for (int r = 0; r < 4; r++) s[nf][r] = 0.0f;

        #pragma unroll
        for (int ks = 0; ks < 4; ks++) {
            uint32_t ah[4], al[4];
            ldsm_x4(ah, sb + a_base + ks * 32);
            ldsm_x4(al, sb + al_base + ks * 32);
            uint32_t bh[8][2], bl[8][2];
            #pragma unroll
            for (int nfp = 0; nfp < 4; nfp++) {
                const uint32_t bo =
                    (uint32_t)(nfp * 16 + b_row16) * AROW + ks * 32 + b_koff;
                ldsm_x4(&bh[2 * nfp][0], S_KH + bo);
                ldsm_x4(&bl[2 * nfp][0], S_KL + bo);
            }
            // product-outer: reuse distance 8 on each acc
            #pragma unroll
            for (int nf = 0; nf < 8; nf++) mma_bf16(s[nf], ah, bh[nf]);
            #pragma unroll
            for (int nf = 0; nf < 8; nf++) mma_bf16(s[nf], ah, bl[nf]);
            #pragma unroll
            for (int nf = 0; nf < 8; nf++) mma_bf16(s[nf], al, bh[nf]);
        }

        if (kb == qb) {
            const int row0 = qb * 64 + warp * 16 + r_in;
            const int row1 = row0 + 8;
            #pragma unroll
            for (int nf = 0; nf < 8; nf++) {
                const int cg = kb * 64 + nf * 8 + c_in;
                if (cg > row0)     s[nf][0] = -1e30f;
                if (cg + 1 > row0) s[nf][1] = -1e30f;
                if (cg > row1)     s[nf][2] = -1e30f;
                if (cg + 1 > row1) s[nf][3] = -1e30f;
            }
        }

        float rmax0 = -1e30f, rmax1 = -1e30f;
        #pragma unroll
        for (int nf = 0; nf < 8; nf++) {
            rmax0 = fmaxf(rmax0, fmaxf(s[nf][0], s[nf][1]));
            rmax1 = fmaxf(rmax1, fmaxf(s[nf][2], s[nf][3]));
        }
        rmax0 = fmaxf(rmax0, __shfl_xor_sync(0xffffffffu, rmax0, 1));
        rmax0 = fmaxf(rmax0, __shfl_xor_sync(0xffffffffu, rmax0, 2));
        rmax1 = fmaxf(rmax1, __shfl_xor_sync(0xffffffffu, rmax1, 1));
        rmax1 = fmaxf(rmax1, __shfl_xor_sync(0xffffffffu, rmax1, 2));
        const float mn0 = fmaxf(m0, rmax0);
        const float mn1 = fmaxf(m1, rmax1);
        const float sc0 = exp2a(m0 - mn0);
        const float sc1 = exp2a(m1 - mn1);

        // P in fp32, kept in s[]
        float rs0 = 0.0f, rs1 = 0.0f;
        #pragma unroll
        for (int nf = 0; nf < 8; nf++) {
            s[nf][0] = exp2a(s[nf][0] - mn0);
            s[nf][1] = exp2a(s[nf][1] - mn0);
            s[nf][2] = exp2a(s[nf][2] - mn1);
            s[nf][3] = exp2a(s[nf][3] - mn1);
            rs0 += s[nf][0] + s[nf][1];
            rs1 += s[nf][2] + s[nf][3];
        }
        rs0 += __shfl_xor_sync(0xffffffffu, rs0, 1);
        rs0 += __shfl_xor_sync(0xffffffffu, rs0, 2);
        rs1 += __shfl_xor_sync(0xffffffffu, rs1, 1);
        rs1 += __shfl_xor_sync(0xffffffffu, rs1, 2);
        l0 = l0 * sc0 + rs0;
        l1 = l1 * sc1 + rs1;
        m0 = mn0; m1 = mn1;
        #pragma unroll
        for (int d = 0; d < 8; d++) {
            O[d][0] *= sc0; O[d][1] *= sc0;
            O[d][2] *= sc1; O[d][3] *= sc1;
        }

        // O += P V : V via x4.trans over 32 kv rows (two ksj per load),
        // df pairs interleaved to break O[] RAW chains.
        #pragma unroll
        for (int pair = 0; pair < 2; pair++) {
            const int k0f = 4 * pair;       // s[] frag base: nf = 4*pair..
            uint32_t ph0[4], pl0[4], ph1[4], pl1[4];
            split2(s[k0f+0][0], s[k0f+0][1], ph0[0], pl0[0]);
            split2(s[k0f+0][2], s[k0f+0][3], ph0[1], pl0[1]);
            split2(s[k0f+1][0], s[k0f+1][1], ph0[2], pl0[2]);
            split2(s[k0f+1][2], s[k0f+1][3], ph0[3], pl0[3]);
            split2(s[k0f+2][0], s[k0f+2][1], ph1[0], pl1[0]);
            split2(s[k0f+2][2], s[k0f+2][3], ph1[1], pl1[1]);
            split2(s[k0f+3][0], s[k0f+3][1], ph1[2], pl1[2]);
            split2(s[k0f+3][2], s[k0f+3][3], ph1[3], pl1[3]);

            const uint32_t vrow = (uint32_t)(pair * 32 + lane) * AROW;
            #pragma unroll
            for (int dfp = 0; dfp < 4; dfp++) {
                const int df0 = 2 * dfp, df1 = 2 * dfp + 1;
                uint32_t vha[4], vla[4], vhb[4], vlb[4];
                ldsm_x4t(vha, S_VH + vrow + df0 * 16);
                ldsm_x4t(vla, S_VL + vrow + df0 * 16);
                ldsm_x4t(vhb, S_VH + vrow + df1 * 16);
                ldsm_x4t(vlb, S_VL + vrow + df1 * 16);
                mma_bf16(O[df0], ph0, &vha[0]);
                mma_bf16(O[df1], ph0, &vhb[0]);
                mma_bf16(O[df0], ph1, &vha[2]);
                mma_bf16(O[df1], ph1, &vhb[2]);
                mma_bf16(O[df0], ph0, &vla[0]);
                mma_bf16(O[df1], ph0, &vlb[0]);
                mma_bf16(O[df0], ph1, &vla[2]);
                mma_bf16(O[df1], ph1, &vlb[2]);
                mma_bf16(O[df0], pl0, &vha[0]);
                mma_bf16(O[df1], pl0, &vhb[0]);
                mma_bf16(O[df0], pl1, &vha[2]);
                mma_bf16(O[df1], pl1, &vhb[2]);
            }
        }
    }

    const float inv0 = 1.0f / l0;
    const float inv1 = 1.0f / l1;
    const int row0 = qb * 64 + warp * 16 + r_in;
    #pragma unroll
    for (int df = 0; df < 8; df++) {
        const size_t col = hcol + df * 8 + c_in;
        uint32_t h0, lo0, h1, lo1;
        split2(O[df][0] * inv0, O[df][1] * inv0, h0, lo0);
        split2(O[df][2] * inv1, O[df][3] * inv1, h1, lo1);
        *(uint32_t*)(Chi + (rbase + row0) * H + col) = h0;
        *(uint32_t*)(Clo + (rbase + row0) * H + col) = lo0;
        *(uint32_t*)(Chi + (rbase + row0 + 8) * H + col) = h1;
        *(uint32_t*)(Clo + (rbase + row0 + 8) * H + col) = lo1;
    }
}

// ---------------------------------------------------------------------------
extern "C" void kernel_launch(void* const* d_in, const int* in_sizes, int n_in,
                              void* d_out, int out_size)
{
    const float* x  = (const float*)d_in[0];
    const float* Wq = (const float*)d_in[1];
    const float* bq = (const float*)d_in[2];
    const float* Wk = (const float*)d_in[3];
    const float* bk = (const float*)d_in[4];
    const float* Wv = (const float*)d_in[5];
    const float* bv = (const float*)d_in[6];
    const float* Wo = (const float*)d_in[7];
    const float* bo = (const float*)d_in[8];
    float* out = (float*)d_out;

    cudaFuncSetAttribute(gemm_qkv,
                         cudaFuncAttributeMaxDynamicSharedMemorySize, GEMM_SMEM);
    cudaFuncSetAttribute(gemm_o,
                         cudaFuncAttributeMaxDynamicSharedMemorySize, GEMM_SMEM);
    cudaFuncSetAttribute(attn_hmma,
                         cudaFuncAttributeMaxDynamicSharedMemorySize, ATTN_SMEM);

    __nv_bfloat16 *qhi, *qlo, *khi, *klo, *vhi, *vlo, *chi, *clo;
    __nv_bfloat16 *xhi, *xlo, *wthi, *wtlo;
    cudaGetSymbolAddress((void**)&qhi, g_Qhi);
    cudaGetSymbolAddress((void**)&qlo, g_Qlo);
    cudaGetSymbolAddress((void**)&khi, g_Khi);
    cudaGetSymbolAddress((void**)&klo, g_Klo);
    cudaGetSymbolAddress((void**)&vhi, g_Vhi);
    cudaGetSymbolAddress((void**)&vlo, g_Vlo);
    cudaGetSymbolAddress((void**)&chi, g_chi);
    cudaGetSymbolAddress((void**)&clo, g_clo);
    cudaGetSymbolAddress((void**)&xhi, g_xhi);
    cudaGetSymbolAddress((void**)&xlo, g_xlo);
    cudaGetSymbolAddress((void**)&wthi, g_WThi);
    cudaGetSymbolAddress((void**)&wtlo, g_WTlo);

    const int nelem = MTOT * H;
    const size_t WSZ = (size_t)H * H;

    split_bf16_v4<<<(nelem / 4 + 255) / 256, 256>>>(x, xhi, xlo, nelem / 4);
    dim3 tgrid(H / 32, H / 32, 4), tblk(32, 8);
    transpose_split4<<<tgrid, tblk>>>(Wq, Wk, Wv, Wo, wthi, wtlo);

    dim3 qkvgrid(3 * H / 128, MTOT / 128);   // (24, 32)
    gemm_qkv<<<qkvgrid, 256, GEMM_SMEM>>>(xhi, xlo, wthi, wtlo,
        bq, bk, bv, qhi, qlo, khi, klo, vhi, vlo);

    dim3 agrid(SEQ / 64, BSZ * NH);          // (32, 32)
    attn_hmma<<<agrid, 128, ATTN_SMEM>>>(qhi, qlo, khi, klo, vhi, vlo, chi, clo);

    dim3 ogrid(H / 128, MTOT / 128);         // (8, 32)
    gemm_o<<<ogrid, 256, GEMM_SMEM>>>(chi, clo, wthi + 3 * WSZ, wtlo + 3 * WSZ,
                                      bo, out);
}